// round 6
// baseline (speedup 1.0000x reference)
#include <cuda_runtime.h>
#include <cstdint>

#define B_  8
#define C_  64
#define T_  12
#define N_  512
#define G_  (B_ * T_)      // 96
#define H_  4
#define CO_ 64
#define HC_ (H_ * CO_)     // 256
#define NEG_SLOPE 0.2f
#define EMAX 16384

typedef unsigned long long ull;

// ---------------- device scratch ----------------
__device__ float g_xt[(size_t)G_ * N_ * C_];     // [G,N,64]
__device__ float g_z [(size_t)G_ * N_ * HC_];    // [G,N,256]
__device__ float g_asrc[(size_t)G_ * N_ * H_];   // [G,N,4]
__device__ float g_adst[(size_t)G_ * N_ * H_];
__device__ float g_u[2 * H_ * C_];               // [src/dst][h][c]
__device__ ull   g_Wtp[128 * CO_];               // [kp][co] = (Wt[2kp][co], Wt[2kp+1][co])
__device__ int   g_rowptr[N_ + 1];
__device__ int   g_col[EMAX];

__device__ __forceinline__ float lrelu(float x) {
    return x > 0.0f ? x : NEG_SLOPE * x;
}
__device__ __forceinline__ ull pack2(float lo, float hi) {
    ull d;
    asm("mov.b64 %0, {%1, %2};" : "=l"(d) : "r"(__float_as_uint(lo)), "r"(__float_as_uint(hi)));
    return d;
}
__device__ __forceinline__ void unpack2(ull v, float& lo, float& hi) {
    unsigned a, b;
    asm("mov.b64 {%0, %1}, %2;" : "=r"(a), "=r"(b) : "l"(v));
    lo = __uint_as_float(a); hi = __uint_as_float(b);
}
__device__ __forceinline__ ull fma2(ull a, ull b, ull c) {
    ull d;
    asm("fma.rn.f32x2 %0, %1, %2, %3;" : "=l"(d) : "l"(a), "l"(b), "l"(c));
    return d;
}

// ============================================================
// K0: setup. block 0: CSR build. block 1: prep u + Wtp. 512 thr.
// ============================================================
__global__ void setup_kernel(const int* __restrict__ ei, int E,
                             const float* __restrict__ W,
                             const float* __restrict__ att_src,
                             const float* __restrict__ att_dst) {
    int tid = threadIdx.x;
    if (blockIdx.x == 0) {
        __shared__ int cnt[N_];
        __shared__ int cur[N_];
        __shared__ int wsum[16];
        cnt[tid] = 0;
        __syncthreads();
        const int* dst = ei + E;
        for (int e = tid; e < E; e += N_) atomicAdd(&cnt[dst[e]], 1);
        __syncthreads();

        int v = cnt[tid];
        int lane = tid & 31, wid = tid >> 5;
        int inc = v;
        #pragma unroll
        for (int o = 1; o < 32; o <<= 1) {
            int u = __shfl_up_sync(0xffffffffu, inc, o);
            if (lane >= o) inc += u;
        }
        if (lane == 31) wsum[wid] = inc;
        __syncthreads();
        if (wid == 0 && lane < 16) {
            int ws = wsum[lane];
            int wi = ws;
            #pragma unroll
            for (int o = 1; o < 16; o <<= 1) {
                int u = __shfl_up_sync(0x0000ffffu, wi, o);
                if (lane >= o) wi += u;
            }
            wsum[lane] = wi - ws;
        }
        __syncthreads();
        int excl = inc - v + wsum[wid];
        g_rowptr[tid] = excl;
        cur[tid] = excl;
        if (tid == N_ - 1) g_rowptr[N_] = excl + v;
        __syncthreads();

        for (int e = tid; e < E; e += N_) {
            int d = dst[e];
            int p = atomicAdd(&cur[d], 1);
            g_col[p] = ei[e];
        }
    } else {
        __shared__ float satt[2 * H_ * CO_];
        satt[tid] = (tid < 256) ? att_src[tid] : att_dst[tid - 256];
        __syncthreads();

        {
            int k = tid;                 // 512 = 2*4*64
            int p = k >> 8;
            int h = (k >> 6) & 3;
            int c = k & 63;
            const float* wrow = W + (size_t)c * HC_ + h * CO_;
            const float* av = satt + p * 256 + h * CO_;
            float s = 0.0f;
            #pragma unroll 16
            for (int co = 0; co < CO_; co++) s += wrow[co] * av[co];
            g_u[k] = s;
        }
        for (int idx = tid; idx < 128 * CO_; idx += 512) {
            int kp = idx >> 6;
            int co = idx & 63;
            int k0 = kp * 2;
            int h = k0 >> 6, c0 = k0 & 63;
            float w0 = 0.25f * W[(size_t)c0 * HC_ + h * CO_ + co];
            float w1 = 0.25f * W[(size_t)(c0 + 1) * HC_ + h * CO_ + co];
            g_Wtp[idx] = pack2(w0, w1);
        }
    }
}

// ============================================================
// K1: per g: transpose x -> xt, asrc/adst = x . u
// grid (4, 96), block 256.
// ============================================================
__global__ void xt_asrc_kernel(const float* __restrict__ x) {
    __shared__ float xs[64][129];
    __shared__ float su[8][64];
    int g  = blockIdx.y;
    int n0 = blockIdx.x * 128;
    int b  = g / T_;
    int t  = g - b * T_;
    int tid = threadIdx.x;

    for (int i = tid; i < 512; i += 256) su[i >> 6][i & 63] = g_u[i];
    #pragma unroll
    for (int i = tid; i < 64 * 32; i += 256) {
        int c = i >> 5, q = i & 31;
        float4 v = *(const float4*)(x + (((size_t)b * C_ + c) * T_ + t) * N_ + n0 + q * 4);
        xs[c][q * 4 + 0] = v.x; xs[c][q * 4 + 1] = v.y;
        xs[c][q * 4 + 2] = v.z; xs[c][q * 4 + 3] = v.w;
    }
    __syncthreads();

    {
        int n = tid & 127;
        int p = tid >> 7;
        float a0 = 0.f, a1 = 0.f, a2 = 0.f, a3 = 0.f;
        #pragma unroll 16
        for (int c = 0; c < 64; c++) {
            float xv = xs[c][n];
            a0 = fmaf(xv, su[p * 4 + 0][c], a0);
            a1 = fmaf(xv, su[p * 4 + 1][c], a1);
            a2 = fmaf(xv, su[p * 4 + 2][c], a2);
            a3 = fmaf(xv, su[p * 4 + 3][c], a3);
        }
        float* dstp = (p == 0 ? g_asrc : g_adst) + ((size_t)g * N_ + n0 + n) * H_;
        dstp[0] = a0; dstp[1] = a1; dstp[2] = a2; dstp[3] = a3;
    }

    #pragma unroll
    for (int i = tid; i < 128 * 16; i += 256) {
        int n = i >> 4, q = i & 15;
        float4 v = {xs[q * 4 + 0][n], xs[q * 4 + 1][n], xs[q * 4 + 2][n], xs[q * 4 + 3][n]};
        *(float4*)(g_xt + ((size_t)g * N_ + n0 + n) * C_ + q * 4) = v;
    }
}

// ============================================================
// K2: aggregate in x-space, warp per (g,dst). (unchanged)
// ============================================================
__global__ void __launch_bounds__(256) aggregate_kernel() {
    __shared__ float4 s_as[N_];
    __shared__ ull    s_wp[8][32][4];
    __shared__ int    s_src[8][32];
    int g    = blockIdx.y;
    int tid  = threadIdx.x;
    int warp = tid >> 5, lane = tid & 31;

    const float4* asrc_g = (const float4*)(g_asrc + (size_t)g * N_ * H_);
    for (int i = tid; i < N_; i += 256) s_as[i] = asrc_g[i];
    __syncthreads();

    int dst   = (blockIdx.x << 3) + warp;
    int start = g_rowptr[dst];
    int end   = g_rowptr[dst + 1];

    float4 ad = *(const float4*)(g_adst + ((size_t)g * N_ + dst) * H_);
    float4 sa = s_as[dst];
    float ws0 = __expf(lrelu(sa.x + ad.x));
    float ws1 = __expf(lrelu(sa.y + ad.y));
    float ws2 = __expf(lrelu(sa.z + ad.z));
    float ws3 = __expf(lrelu(sa.w + ad.w));

    const ull* xgu = (const ull*)(g_xt + (size_t)g * N_ * C_);

    ull xdv = xgu[(size_t)dst * 32 + lane];
    ull acc0 = fma2(pack2(ws0, ws0), xdv, 0ULL);
    ull acc1 = fma2(pack2(ws1, ws1), xdv, 0ULL);
    ull acc2 = fma2(pack2(ws2, ws2), xdv, 0ULL);
    ull acc3 = fma2(pack2(ws3, ws3), xdv, 0ULL);

    float p0 = 0.f, p1 = 0.f, p2 = 0.f, p3 = 0.f;

    for (int base = start; base < end; base += 32) {
        int e = base + lane;
        int src = 0;
        float w0 = 0.f, w1 = 0.f, w2 = 0.f, w3 = 0.f;
        if (e < end) {
            src = g_col[e];
            float4 a = s_as[src];
            w0 = __expf(lrelu(a.x + ad.x));
            w1 = __expf(lrelu(a.y + ad.y));
            w2 = __expf(lrelu(a.z + ad.z));
            w3 = __expf(lrelu(a.w + ad.w));
        }
        p0 += w0; p1 += w1; p2 += w2; p3 += w3;
        ulonglong2 pA, pB;
        pA.x = pack2(w0, w0); pA.y = pack2(w1, w1);
        pB.x = pack2(w2, w2); pB.y = pack2(w3, w3);
        *(ulonglong2*)&s_wp[warp][lane][0] = pA;
        *(ulonglong2*)&s_wp[warp][lane][2] = pB;
        s_src[warp][lane] = src;
        __syncwarp();

        int cnt = min(32, end - base);
        int sj = s_src[warp][0];
        ull xv = xgu[(size_t)sj * 32 + lane];
        for (int j = 0; j < cnt; j++) {
            int jn = min(j + 1, cnt - 1);
            int sn = s_src[warp][jn];
            ull xn = xgu[(size_t)sn * 32 + lane];
            ulonglong2 wA = *(const ulonglong2*)&s_wp[warp][j][0];
            ulonglong2 wB = *(const ulonglong2*)&s_wp[warp][j][2];
            acc0 = fma2(wA.x, xv, acc0);
            acc1 = fma2(wA.y, xv, acc1);
            acc2 = fma2(wB.x, xv, acc2);
            acc3 = fma2(wB.y, xv, acc3);
            xv = xn;
        }
        __syncwarp();
    }

    #pragma unroll
    for (int o = 16; o > 0; o >>= 1) {
        p0 += __shfl_xor_sync(0xffffffffu, p0, o);
        p1 += __shfl_xor_sync(0xffffffffu, p1, o);
        p2 += __shfl_xor_sync(0xffffffffu, p2, o);
        p3 += __shfl_xor_sync(0xffffffffu, p3, o);
    }
    float i0 = 1.0f / (p0 + ws0);
    float i1 = 1.0f / (p1 + ws1);
    float i2 = 1.0f / (p2 + ws2);
    float i3 = 1.0f / (p3 + ws3);

    float lo, hi;
    float* zp = g_z + ((size_t)g * N_ + dst) * HC_ + 2 * lane;
    unpack2(acc0, lo, hi); *(float2*)(zp +   0) = make_float2(lo * i0, hi * i0);
    unpack2(acc1, lo, hi); *(float2*)(zp +  64) = make_float2(lo * i1, hi * i1);
    unpack2(acc2, lo, hi); *(float2*)(zp + 128) = make_float2(lo * i2, hi * i2);
    unpack2(acc3, lo, hi); *(float2*)(zp + 192) = make_float2(lo * i3, hi * i3);
}

// ============================================================
// K3: out = z @ Wt + bias -> [B,Co,T,N].
// Block 128 thr, tile 64n x 64co; thread tile 4n x 8co.
// tid = ng*8 + cg (ng 0..15, cg 0..7). grid (8, 96).
// ============================================================
#define SF_PAD 68
__global__ void __launch_bounds__(128) gemm2_kernel(const float* __restrict__ bias,
                                                    float* __restrict__ out) {
    __shared__ __align__(16) float s_f[64][SF_PAD];   // z chunk [n][k]; reused as os[co][n]
    __shared__ __align__(16) ull   s_w[32][64];       // w chunk [kp][co]

    int g  = blockIdx.y;
    int n0 = blockIdx.x * 64;
    int b  = g / T_;
    int t  = g - b * T_;
    int tid = threadIdx.x;
    int ng = tid >> 3;    // 0..15
    int cg = tid & 7;     // 0..7

    ull accA[4][4], accB[4][4];
    #pragma unroll
    for (int i = 0; i < 4; i++)
        #pragma unroll
        for (int j = 0; j < 4; j++) { accA[i][j] = 0ULL; accB[i][j] = 0ULL; }

    const float* zrow0 = g_z + ((size_t)g * N_ + n0) * HC_;

    for (int kk = 0; kk < 4; kk++) {
        __syncthreads();
        #pragma unroll
        for (int i = tid; i < 64 * 16; i += 128) {
            int n = i >> 4, q = i & 15;
            float4 v = *(const float4*)(zrow0 + (size_t)n * HC_ + kk * 64 + q * 4);
            *(float4*)&s_f[n][q * 4] = v;
        }
        #pragma unroll
        for (int i = tid; i < 32 * 32; i += 128) {
            int kp = i >> 5, c2 = i & 31;
            ulonglong2 v = *(const ulonglong2*)(g_Wtp + (size_t)(kk * 32 + kp) * CO_ + c2 * 2);
            *(ulonglong2*)&s_w[kp][c2 * 2] = v;
        }
        __syncthreads();

        #pragma unroll 8
        for (int kp = 0; kp < 32; kp++) {
            ulonglong2 wA = *(const ulonglong2*)&s_w[kp][cg * 8];
            ulonglong2 wB = *(const ulonglong2*)&s_w[kp][cg * 8 + 2];
            ulonglong2 wC = *(const ulonglong2*)&s_w[kp][cg * 8 + 4];
            ulonglong2 wD = *(const ulonglong2*)&s_w[kp][cg * 8 + 6];
            #pragma unroll
            for (int i = 0; i < 4; i++) {
                ull zv = *(const ull*)&s_f[ng * 4 + i][kp * 2];  // broadcast pair
                accA[i][0] = fma2(zv, wA.x, accA[i][0]);
                accA[i][1] = fma2(zv, wA.y, accA[i][1]);
                accA[i][2] = fma2(zv, wB.x, accA[i][2]);
                accA[i][3] = fma2(zv, wB.y, accA[i][3]);
                accB[i][0] = fma2(zv, wC.x, accB[i][0]);
                accB[i][1] = fma2(zv, wC.y, accB[i][1]);
                accB[i][2] = fma2(zv, wD.x, accB[i][2]);
                accB[i][3] = fma2(zv, wD.y, accB[i][3]);
            }
        }
    }
    __syncthreads();   // s_f dead; reuse as os[co][n]

    float (*os)[SF_PAD] = s_f;
    #pragma unroll
    for (int i = 0; i < 4; i++) {
        int n = ng * 4 + i;
        #pragma unroll
        for (int j = 0; j < 4; j++) {
            float lo, hi;
            unpack2(accA[i][j], lo, hi);
            os[cg * 8 + j][n] = lo + hi;
            unpack2(accB[i][j], lo, hi);
            os[cg * 8 + 4 + j][n] = lo + hi;
        }
    }
    __syncthreads();

    #pragma unroll
    for (int i = tid; i < 64 * 16; i += 128) {
        int co = i >> 4, q = i & 15;
        float bv = __ldg(&bias[co]);
        float4 v = *(const float4*)&os[co][q * 4];
        v.x += bv; v.y += bv; v.z += bv; v.w += bv;
        *(float4*)(out + (((size_t)b * CO_ + co) * T_ + t) * N_ + n0 + q * 4) = v;
    }
}

// ============================================================
extern "C" void kernel_launch(void* const* d_in, const int* in_sizes, int n_in,
                              void* d_out, int out_size) {
    const float* x        = (const float*)d_in[0];
    const int*   ei       = (const int*)  d_in[1];
    const float* W        = (const float*)d_in[2];
    const float* att_src  = (const float*)d_in[3];
    const float* att_dst  = (const float*)d_in[4];
    const float* bias     = (const float*)d_in[5];
    float*       out      = (float*)d_out;
    int E = in_sizes[1] / 2;

    setup_kernel<<<2, 512>>>(ei, E, W, att_src, att_dst);
    xt_asrc_kernel<<<dim3(N_ / 128, G_), 256>>>(x);
    aggregate_kernel<<<dim3(N_ / 8, G_), 256>>>();
    gemm2_kernel<<<dim3(N_ / 64, G_), 128>>>(bias, out);
}

// round 7
// speedup vs baseline: 1.1618x; 1.1618x over previous
#include <cuda_runtime.h>
#include <cstdint>

#define B_  8
#define C_  64
#define T_  12
#define N_  512
#define G_  (B_ * T_)      // 96
#define H_  4
#define CO_ 64
#define HC_ (H_ * CO_)     // 256
#define NEG_SLOPE 0.2f
#define EMAX 16384

typedef unsigned long long ull;

// ---------------- device scratch ----------------
__device__ float g_xt[(size_t)G_ * N_ * C_];     // [G,N,64]
__device__ float g_z [(size_t)G_ * N_ * HC_];    // [G,N,256]
__device__ float g_asrc[(size_t)G_ * N_ * H_];   // [G,N,4]
__device__ float g_adst[(size_t)G_ * N_ * H_];
__device__ float g_u[2 * H_ * C_];               // [src/dst][h][c]
__device__ ull   g_Wdup[HC_ * CO_];              // [k][co] = (wt, wt) duplicated
__device__ int   g_rowptr[N_ + 1];
__device__ int   g_col[EMAX];

__device__ __forceinline__ float lrelu(float x) {
    return x > 0.0f ? x : NEG_SLOPE * x;
}
__device__ __forceinline__ ull pack2(float lo, float hi) {
    ull d;
    asm("mov.b64 %0, {%1, %2};" : "=l"(d) : "r"(__float_as_uint(lo)), "r"(__float_as_uint(hi)));
    return d;
}
__device__ __forceinline__ void unpack2(ull v, float& lo, float& hi) {
    unsigned a, b;
    asm("mov.b64 {%0, %1}, %2;" : "=r"(a), "=r"(b) : "l"(v));
    lo = __uint_as_float(a); hi = __uint_as_float(b);
}
__device__ __forceinline__ ull fma2(ull a, ull b, ull c) {
    ull d;
    asm("fma.rn.f32x2 %0, %1, %2, %3;" : "=l"(d) : "l"(a), "l"(b), "l"(c));
    return d;
}

// ============================================================
// K0: setup. block 0: CSR build. block 1: prep u + Wdup. 512 thr.
// ============================================================
__global__ void setup_kernel(const int* __restrict__ ei, int E,
                             const float* __restrict__ W,
                             const float* __restrict__ att_src,
                             const float* __restrict__ att_dst) {
    int tid = threadIdx.x;
    if (blockIdx.x == 0) {
        __shared__ int cnt[N_];
        __shared__ int cur[N_];
        __shared__ int wsum[16];
        cnt[tid] = 0;
        __syncthreads();
        const int* dst = ei + E;
        for (int e = tid; e < E; e += N_) atomicAdd(&cnt[dst[e]], 1);
        __syncthreads();

        int v = cnt[tid];
        int lane = tid & 31, wid = tid >> 5;
        int inc = v;
        #pragma unroll
        for (int o = 1; o < 32; o <<= 1) {
            int u = __shfl_up_sync(0xffffffffu, inc, o);
            if (lane >= o) inc += u;
        }
        if (lane == 31) wsum[wid] = inc;
        __syncthreads();
        if (wid == 0 && lane < 16) {
            int ws = wsum[lane];
            int wi = ws;
            #pragma unroll
            for (int o = 1; o < 16; o <<= 1) {
                int u = __shfl_up_sync(0x0000ffffu, wi, o);
                if (lane >= o) wi += u;
            }
            wsum[lane] = wi - ws;
        }
        __syncthreads();
        int excl = inc - v + wsum[wid];
        g_rowptr[tid] = excl;
        cur[tid] = excl;
        if (tid == N_ - 1) g_rowptr[N_] = excl + v;
        __syncthreads();

        for (int e = tid; e < E; e += N_) {
            int d = dst[e];
            int p = atomicAdd(&cur[d], 1);
            g_col[p] = ei[e];
        }
    } else {
        __shared__ float satt[2 * H_ * CO_];
        satt[tid] = (tid < 256) ? att_src[tid] : att_dst[tid - 256];
        __syncthreads();

        {
            int k = tid;                 // 512 = 2*4*64
            int p = k >> 8;
            int h = (k >> 6) & 3;
            int c = k & 63;
            const float* wrow = W + (size_t)c * HC_ + h * CO_;
            const float* av = satt + p * 256 + h * CO_;
            float s = 0.0f;
            #pragma unroll 16
            for (int co = 0; co < CO_; co++) s += wrow[co] * av[co];
            g_u[k] = s;
        }
        // Wdup[k][co] = (wt, wt), wt = 0.25*W[c][h*64+co], k = h*64+c
        for (int idx = tid; idx < HC_ * CO_; idx += 512) {
            int k  = idx >> 6;
            int co = idx & 63;
            int h = k >> 6, c = k & 63;
            float wt = 0.25f * W[(size_t)c * HC_ + h * CO_ + co];
            g_Wdup[idx] = pack2(wt, wt);
        }
    }
}

// ============================================================
// K1: per g: transpose x -> xt, asrc/adst = x . u
// grid (4, 96), block 256.
// ============================================================
__global__ void xt_asrc_kernel(const float* __restrict__ x) {
    __shared__ float xs[64][129];
    __shared__ float su[8][64];
    int g  = blockIdx.y;
    int n0 = blockIdx.x * 128;
    int b  = g / T_;
    int t  = g - b * T_;
    int tid = threadIdx.x;

    for (int i = tid; i < 512; i += 256) su[i >> 6][i & 63] = g_u[i];
    #pragma unroll
    for (int i = tid; i < 64 * 32; i += 256) {
        int c = i >> 5, q = i & 31;
        float4 v = *(const float4*)(x + (((size_t)b * C_ + c) * T_ + t) * N_ + n0 + q * 4);
        xs[c][q * 4 + 0] = v.x; xs[c][q * 4 + 1] = v.y;
        xs[c][q * 4 + 2] = v.z; xs[c][q * 4 + 3] = v.w;
    }
    __syncthreads();

    {
        int n = tid & 127;
        int p = tid >> 7;
        float a0 = 0.f, a1 = 0.f, a2 = 0.f, a3 = 0.f;
        #pragma unroll 16
        for (int c = 0; c < 64; c++) {
            float xv = xs[c][n];
            a0 = fmaf(xv, su[p * 4 + 0][c], a0);
            a1 = fmaf(xv, su[p * 4 + 1][c], a1);
            a2 = fmaf(xv, su[p * 4 + 2][c], a2);
            a3 = fmaf(xv, su[p * 4 + 3][c], a3);
        }
        float* dstp = (p == 0 ? g_asrc : g_adst) + ((size_t)g * N_ + n0 + n) * H_;
        dstp[0] = a0; dstp[1] = a1; dstp[2] = a2; dstp[3] = a3;
    }

    #pragma unroll
    for (int i = tid; i < 128 * 16; i += 256) {
        int n = i >> 4, q = i & 15;
        float4 v = {xs[q * 4 + 0][n], xs[q * 4 + 1][n], xs[q * 4 + 2][n], xs[q * 4 + 3][n]};
        *(float4*)(g_xt + ((size_t)g * N_ + n0 + n) * C_ + q * 4) = v;
    }
}

// ============================================================
// K2: aggregate in x-space, warp per (g,dst). (unchanged, proven)
// ============================================================
__global__ void __launch_bounds__(256) aggregate_kernel() {
    __shared__ float4 s_as[N_];
    __shared__ ull    s_wp[8][32][4];
    __shared__ int    s_src[8][32];
    int g    = blockIdx.y;
    int tid  = threadIdx.x;
    int warp = tid >> 5, lane = tid & 31;

    const float4* asrc_g = (const float4*)(g_asrc + (size_t)g * N_ * H_);
    for (int i = tid; i < N_; i += 256) s_as[i] = asrc_g[i];
    __syncthreads();

    int dst   = (blockIdx.x << 3) + warp;
    int start = g_rowptr[dst];
    int end   = g_rowptr[dst + 1];

    float4 ad = *(const float4*)(g_adst + ((size_t)g * N_ + dst) * H_);
    float4 sa = s_as[dst];
    float ws0 = __expf(lrelu(sa.x + ad.x));
    float ws1 = __expf(lrelu(sa.y + ad.y));
    float ws2 = __expf(lrelu(sa.z + ad.z));
    float ws3 = __expf(lrelu(sa.w + ad.w));

    const ull* xgu = (const ull*)(g_xt + (size_t)g * N_ * C_);

    ull xdv = xgu[(size_t)dst * 32 + lane];
    ull acc0 = fma2(pack2(ws0, ws0), xdv, 0ULL);
    ull acc1 = fma2(pack2(ws1, ws1), xdv, 0ULL);
    ull acc2 = fma2(pack2(ws2, ws2), xdv, 0ULL);
    ull acc3 = fma2(pack2(ws3, ws3), xdv, 0ULL);

    float p0 = 0.f, p1 = 0.f, p2 = 0.f, p3 = 0.f;

    for (int base = start; base < end; base += 32) {
        int e = base + lane;
        int src = 0;
        float w0 = 0.f, w1 = 0.f, w2 = 0.f, w3 = 0.f;
        if (e < end) {
            src = g_col[e];
            float4 a = s_as[src];
            w0 = __expf(lrelu(a.x + ad.x));
            w1 = __expf(lrelu(a.y + ad.y));
            w2 = __expf(lrelu(a.z + ad.z));
            w3 = __expf(lrelu(a.w + ad.w));
        }
        p0 += w0; p1 += w1; p2 += w2; p3 += w3;
        ulonglong2 pA, pB;
        pA.x = pack2(w0, w0); pA.y = pack2(w1, w1);
        pB.x = pack2(w2, w2); pB.y = pack2(w3, w3);
        *(ulonglong2*)&s_wp[warp][lane][0] = pA;
        *(ulonglong2*)&s_wp[warp][lane][2] = pB;
        s_src[warp][lane] = src;
        __syncwarp();

        int cnt = min(32, end - base);
        int sj = s_src[warp][0];
        ull xv = xgu[(size_t)sj * 32 + lane];
        for (int j = 0; j < cnt; j++) {
            int jn = min(j + 1, cnt - 1);
            int sn = s_src[warp][jn];
            ull xn = xgu[(size_t)sn * 32 + lane];
            ulonglong2 wA = *(const ulonglong2*)&s_wp[warp][j][0];
            ulonglong2 wB = *(const ulonglong2*)&s_wp[warp][j][2];
            acc0 = fma2(wA.x, xv, acc0);
            acc1 = fma2(wA.y, xv, acc1);
            acc2 = fma2(wB.x, xv, acc2);
            acc3 = fma2(wB.y, xv, acc3);
            xv = xn;
        }
        __syncwarp();
    }

    #pragma unroll
    for (int o = 16; o > 0; o >>= 1) {
        p0 += __shfl_xor_sync(0xffffffffu, p0, o);
        p1 += __shfl_xor_sync(0xffffffffu, p1, o);
        p2 += __shfl_xor_sync(0xffffffffu, p2, o);
        p3 += __shfl_xor_sync(0xffffffffu, p3, o);
    }
    float i0 = 1.0f / (p0 + ws0);
    float i1 = 1.0f / (p1 + ws1);
    float i2 = 1.0f / (p2 + ws2);
    float i3 = 1.0f / (p3 + ws3);

    float lo, hi;
    float* zp = g_z + ((size_t)g * N_ + dst) * HC_ + 2 * lane;
    unpack2(acc0, lo, hi); *(float2*)(zp +   0) = make_float2(lo * i0, hi * i0);
    unpack2(acc1, lo, hi); *(float2*)(zp +  64) = make_float2(lo * i1, hi * i1);
    unpack2(acc2, lo, hi); *(float2*)(zp + 128) = make_float2(lo * i2, hi * i2);
    unpack2(acc3, lo, hi); *(float2*)(zp + 192) = make_float2(lo * i3, hi * i3);
}

// ============================================================
// K3: out = z @ Wt + bias -> [B,Co,T,N].
// n-paired f32x2: s_z transposed [k][n], weights pre-duplicated.
// Block 128 thr (8 ng x 16 cg); tile 64n x 64co; thread 8n x 4co.
// grid (8, 96).
// ============================================================
#define KC 32
__global__ void __launch_bounds__(128) gemm2_kernel(const float* __restrict__ bias,
                                                    float* __restrict__ out) {
    // overlay: s_z + s_w during mainloop, os in epilogue
    __shared__ __align__(16) char sm[KC * 68 * 4 + KC * 64 * 8];  // 8704 + 16384 = 25088
    float (*s_z)[68] = (float(*)[68])sm;                  // [k][n] transposed chunk
    ull   (*s_w)[64] = (ull(*)[64])(sm + KC * 68 * 4);    // [k][co] dup pairs
    float (*os)[68]  = (float(*)[68])sm;                  // epilogue [co][n] (17408 B)

    int g  = blockIdx.y;
    int n0 = blockIdx.x * 64;
    int b  = g / T_;
    int t  = g - b * T_;
    int tid = threadIdx.x;
    int ng = tid >> 4;    // 0..7  -> n rows ng*8 .. ng*8+7 (4 pairs)
    int cg = tid & 15;    // 0..15 -> co cols cg*4 .. cg*4+3

    ull acc[4][4];        // [n-pair][co]
    #pragma unroll
    for (int i = 0; i < 4; i++)
        #pragma unroll
        for (int j = 0; j < 4; j++) acc[i][j] = 0ULL;

    const float* zrow = g_z + ((size_t)g * N_ + n0) * HC_;

    for (int kk = 0; kk < 8; kk++) {
        __syncthreads();
        // stage z transposed: read z[n][k] float4 along k, scatter to s_z[k][n]
        {
            int n = tid & 63, kq0 = tid >> 6;   // kq0 in {0,1}
            #pragma unroll
            for (int kq = kq0; kq < 8; kq += 2) {
                float4 v = *(const float4*)(zrow + (size_t)n * HC_ + kk * KC + kq * 4);
                s_z[kq * 4 + 0][n] = v.x;
                s_z[kq * 4 + 1][n] = v.y;
                s_z[kq * 4 + 2][n] = v.z;
                s_z[kq * 4 + 3][n] = v.w;
            }
        }
        // stage w: [32 k][64 co] ull
        #pragma unroll
        for (int i = tid; i < 32 * 32; i += 128) {
            int k = i >> 5, c2 = i & 31;
            ulonglong2 v = *(const ulonglong2*)(g_Wdup + (size_t)(kk * KC + k) * CO_ + c2 * 2);
            *(ulonglong2*)&s_w[k][c2 * 2] = v;
        }
        __syncthreads();

        #pragma unroll 4
        for (int k = 0; k < KC; k++) {
            ulonglong2 zA = *(const ulonglong2*)&s_z[k][ng * 8];      // pairs 0,1
            ulonglong2 zB = *(const ulonglong2*)&s_z[k][ng * 8 + 4];  // pairs 2,3
            ulonglong2 wA = *(const ulonglong2*)&s_w[k][cg * 4];      // co 0,1
            ulonglong2 wB = *(const ulonglong2*)&s_w[k][cg * 4 + 2];  // co 2,3
            acc[0][0] = fma2(zA.x, wA.x, acc[0][0]);
            acc[0][1] = fma2(zA.x, wA.y, acc[0][1]);
            acc[0][2] = fma2(zA.x, wB.x, acc[0][2]);
            acc[0][3] = fma2(zA.x, wB.y, acc[0][3]);
            acc[1][0] = fma2(zA.y, wA.x, acc[1][0]);
            acc[1][1] = fma2(zA.y, wA.y, acc[1][1]);
            acc[1][2] = fma2(zA.y, wB.x, acc[1][2]);
            acc[1][3] = fma2(zA.y, wB.y, acc[1][3]);
            acc[2][0] = fma2(zB.x, wA.x, acc[2][0]);
            acc[2][1] = fma2(zB.x, wA.y, acc[2][1]);
            acc[2][2] = fma2(zB.x, wB.x, acc[2][2]);
            acc[2][3] = fma2(zB.x, wB.y, acc[2][3]);
            acc[3][0] = fma2(zB.y, wA.x, acc[3][0]);
            acc[3][1] = fma2(zB.y, wA.y, acc[3][1]);
            acc[3][2] = fma2(zB.y, wB.x, acc[3][2]);
            acc[3][3] = fma2(zB.y, wB.y, acc[3][3]);
        }
    }
    __syncthreads();   // s_z/s_w dead; reuse as os[co][n]

    #pragma unroll
    for (int p = 0; p < 4; p++) {
        int n = ng * 8 + p * 2;
        #pragma unroll
        for (int j = 0; j < 4; j++) {
            float lo, hi;
            unpack2(acc[p][j], lo, hi);
            os[cg * 4 + j][n]     = lo;   // complete outputs: lo = row n, hi = row n+1
            os[cg * 4 + j][n + 1] = hi;
        }
    }
    __syncthreads();

    #pragma unroll
    for (int i = tid; i < 64 * 16; i += 128) {
        int co = i >> 4, q = i & 15;
        float bv = __ldg(&bias[co]);
        float4 v = *(const float4*)&os[co][q * 4];
        v.x += bv; v.y += bv; v.z += bv; v.w += bv;
        *(float4*)(out + (((size_t)b * CO_ + co) * T_ + t) * N_ + n0 + q * 4) = v;
    }
}

// ============================================================
extern "C" void kernel_launch(void* const* d_in, const int* in_sizes, int n_in,
                              void* d_out, int out_size) {
    const float* x        = (const float*)d_in[0];
    const int*   ei       = (const int*)  d_in[1];
    const float* W        = (const float*)d_in[2];
    const float* att_src  = (const float*)d_in[3];
    const float* att_dst  = (const float*)d_in[4];
    const float* bias     = (const float*)d_in[5];
    float*       out      = (float*)d_out;
    int E = in_sizes[1] / 2;

    setup_kernel<<<2, 512>>>(ei, E, W, att_src, att_dst);
    xt_asrc_kernel<<<dim3(N_ / 128, G_), 256>>>(x);
    aggregate_kernel<<<dim3(N_ / 8, G_), 256>>>();
    gemm2_kernel<<<dim3(N_ / 64, G_), 128>>>(bias, out);
}

// round 8
// speedup vs baseline: 1.3404x; 1.1538x over previous
#include <cuda_runtime.h>
#include <cstdint>

#define B_  8
#define C_  64
#define T_  12
#define N_  512
#define G_  (B_ * T_)      // 96
#define H_  4
#define CO_ 64
#define HC_ (H_ * CO_)     // 256
#define NEG_SLOPE 0.2f
#define EMAX 16384

typedef unsigned long long ull;

// ---------------- device scratch ----------------
__device__ float g_xt[(size_t)G_ * N_ * C_];     // [G,N,64]
__device__ float g_z [(size_t)G_ * N_ * HC_];    // [G,N,256]
__device__ float g_asrc[(size_t)G_ * N_ * H_];   // [G,N,4]
__device__ float g_adst[(size_t)G_ * N_ * H_];
__device__ float g_u[2 * H_ * C_];               // [src/dst][h][c]
__device__ ull   g_Wdup[HC_ * CO_];              // [k][co] = (wt, wt) duplicated
__device__ int   g_rowptr[N_ + 1];
__device__ int   g_col[EMAX];

__device__ __forceinline__ float lrelu(float x) {
    return x > 0.0f ? x : NEG_SLOPE * x;
}
__device__ __forceinline__ ull pack2(float lo, float hi) {
    ull d;
    asm("mov.b64 %0, {%1, %2};" : "=l"(d) : "r"(__float_as_uint(lo)), "r"(__float_as_uint(hi)));
    return d;
}
__device__ __forceinline__ void unpack2(ull v, float& lo, float& hi) {
    unsigned a, b;
    asm("mov.b64 {%0, %1}, %2;" : "=r"(a), "=r"(b) : "l"(v));
    lo = __uint_as_float(a); hi = __uint_as_float(b);
}
__device__ __forceinline__ ull fma2(ull a, ull b, ull c) {
    ull d;
    asm("fma.rn.f32x2 %0, %1, %2, %3;" : "=l"(d) : "l"(a), "l"(b), "l"(c));
    return d;
}

// ============================================================
// K0: setup. block 0: CSR build. block 1: prep u + Wdup. 512 thr.
// ============================================================
__global__ void setup_kernel(const int* __restrict__ ei, int E,
                             const float* __restrict__ W,
                             const float* __restrict__ att_src,
                             const float* __restrict__ att_dst) {
    int tid = threadIdx.x;
    if (blockIdx.x == 0) {
        __shared__ int cnt[N_];
        __shared__ int cur[N_];
        __shared__ int wsum[16];
        cnt[tid] = 0;
        __syncthreads();
        const int* dst = ei + E;
        for (int e = tid; e < E; e += N_) atomicAdd(&cnt[dst[e]], 1);
        __syncthreads();

        int v = cnt[tid];
        int lane = tid & 31, wid = tid >> 5;
        int inc = v;
        #pragma unroll
        for (int o = 1; o < 32; o <<= 1) {
            int u = __shfl_up_sync(0xffffffffu, inc, o);
            if (lane >= o) inc += u;
        }
        if (lane == 31) wsum[wid] = inc;
        __syncthreads();
        if (wid == 0 && lane < 16) {
            int ws = wsum[lane];
            int wi = ws;
            #pragma unroll
            for (int o = 1; o < 16; o <<= 1) {
                int u = __shfl_up_sync(0x0000ffffu, wi, o);
                if (lane >= o) wi += u;
            }
            wsum[lane] = wi - ws;
        }
        __syncthreads();
        int excl = inc - v + wsum[wid];
        g_rowptr[tid] = excl;
        cur[tid] = excl;
        if (tid == N_ - 1) g_rowptr[N_] = excl + v;
        __syncthreads();

        for (int e = tid; e < E; e += N_) {
            int d = dst[e];
            int p = atomicAdd(&cur[d], 1);
            g_col[p] = ei[e];
        }
    } else {
        __shared__ float satt[2 * H_ * CO_];
        satt[tid] = (tid < 256) ? att_src[tid] : att_dst[tid - 256];
        __syncthreads();

        {
            int k = tid;                 // 512 = 2*4*64
            int p = k >> 8;
            int h = (k >> 6) & 3;
            int c = k & 63;
            const float* wrow = W + (size_t)c * HC_ + h * CO_;
            const float* av = satt + p * 256 + h * CO_;
            float s = 0.0f;
            #pragma unroll 16
            for (int co = 0; co < CO_; co++) s += wrow[co] * av[co];
            g_u[k] = s;
        }
        // Wdup[k][co] = (wt, wt), wt = 0.25*W[c][h*64+co], k = h*64+c
        for (int idx = tid; idx < HC_ * CO_; idx += 512) {
            int k  = idx >> 6;
            int co = idx & 63;
            int h = k >> 6, c = k & 63;
            float wt = 0.25f * W[(size_t)c * HC_ + h * CO_ + co];
            g_Wdup[idx] = pack2(wt, wt);
        }
    }
}

// ============================================================
// K1: per g: transpose x -> xt, asrc/adst = x . u
// grid (4, 96), block 256.
// ============================================================
__global__ void xt_asrc_kernel(const float* __restrict__ x) {
    __shared__ float xs[64][129];
    __shared__ float su[8][64];
    int g  = blockIdx.y;
    int n0 = blockIdx.x * 128;
    int b  = g / T_;
    int t  = g - b * T_;
    int tid = threadIdx.x;

    for (int i = tid; i < 512; i += 256) su[i >> 6][i & 63] = g_u[i];
    #pragma unroll
    for (int i = tid; i < 64 * 32; i += 256) {
        int c = i >> 5, q = i & 31;
        float4 v = *(const float4*)(x + (((size_t)b * C_ + c) * T_ + t) * N_ + n0 + q * 4);
        xs[c][q * 4 + 0] = v.x; xs[c][q * 4 + 1] = v.y;
        xs[c][q * 4 + 2] = v.z; xs[c][q * 4 + 3] = v.w;
    }
    __syncthreads();

    {
        int n = tid & 127;
        int p = tid >> 7;
        float a0 = 0.f, a1 = 0.f, a2 = 0.f, a3 = 0.f;
        #pragma unroll 16
        for (int c = 0; c < 64; c++) {
            float xv = xs[c][n];
            a0 = fmaf(xv, su[p * 4 + 0][c], a0);
            a1 = fmaf(xv, su[p * 4 + 1][c], a1);
            a2 = fmaf(xv, su[p * 4 + 2][c], a2);
            a3 = fmaf(xv, su[p * 4 + 3][c], a3);
        }
        float* dstp = (p == 0 ? g_asrc : g_adst) + ((size_t)g * N_ + n0 + n) * H_;
        dstp[0] = a0; dstp[1] = a1; dstp[2] = a2; dstp[3] = a3;
    }

    #pragma unroll
    for (int i = tid; i < 128 * 16; i += 256) {
        int n = i >> 4, q = i & 15;
        float4 v = {xs[q * 4 + 0][n], xs[q * 4 + 1][n], xs[q * 4 + 2][n], xs[q * 4 + 3][n]};
        *(float4*)(g_xt + ((size_t)g * N_ + n0 + n) * C_ + q * 4) = v;
    }
}

// ============================================================
// K2: aggregate in x-space, warp per (g,dst). (unchanged, proven)
// ============================================================
__global__ void __launch_bounds__(256) aggregate_kernel() {
    __shared__ float4 s_as[N_];
    __shared__ ull    s_wp[8][32][4];
    __shared__ int    s_src[8][32];
    int g    = blockIdx.y;
    int tid  = threadIdx.x;
    int warp = tid >> 5, lane = tid & 31;

    const float4* asrc_g = (const float4*)(g_asrc + (size_t)g * N_ * H_);
    for (int i = tid; i < N_; i += 256) s_as[i] = asrc_g[i];
    __syncthreads();

    int dst   = (blockIdx.x << 3) + warp;
    int start = g_rowptr[dst];
    int end   = g_rowptr[dst + 1];

    float4 ad = *(const float4*)(g_adst + ((size_t)g * N_ + dst) * H_);
    float4 sa = s_as[dst];
    float ws0 = __expf(lrelu(sa.x + ad.x));
    float ws1 = __expf(lrelu(sa.y + ad.y));
    float ws2 = __expf(lrelu(sa.z + ad.z));
    float ws3 = __expf(lrelu(sa.w + ad.w));

    const ull* xgu = (const ull*)(g_xt + (size_t)g * N_ * C_);

    ull xdv = xgu[(size_t)dst * 32 + lane];
    ull acc0 = fma2(pack2(ws0, ws0), xdv, 0ULL);
    ull acc1 = fma2(pack2(ws1, ws1), xdv, 0ULL);
    ull acc2 = fma2(pack2(ws2, ws2), xdv, 0ULL);
    ull acc3 = fma2(pack2(ws3, ws3), xdv, 0ULL);

    float p0 = 0.f, p1 = 0.f, p2 = 0.f, p3 = 0.f;

    for (int base = start; base < end; base += 32) {
        int e = base + lane;
        int src = 0;
        float w0 = 0.f, w1 = 0.f, w2 = 0.f, w3 = 0.f;
        if (e < end) {
            src = g_col[e];
            float4 a = s_as[src];
            w0 = __expf(lrelu(a.x + ad.x));
            w1 = __expf(lrelu(a.y + ad.y));
            w2 = __expf(lrelu(a.z + ad.z));
            w3 = __expf(lrelu(a.w + ad.w));
        }
        p0 += w0; p1 += w1; p2 += w2; p3 += w3;
        ulonglong2 pA, pB;
        pA.x = pack2(w0, w0); pA.y = pack2(w1, w1);
        pB.x = pack2(w2, w2); pB.y = pack2(w3, w3);
        *(ulonglong2*)&s_wp[warp][lane][0] = pA;
        *(ulonglong2*)&s_wp[warp][lane][2] = pB;
        s_src[warp][lane] = src;
        __syncwarp();

        int cnt = min(32, end - base);
        int sj = s_src[warp][0];
        ull xv = xgu[(size_t)sj * 32 + lane];
        for (int j = 0; j < cnt; j++) {
            int jn = min(j + 1, cnt - 1);
            int sn = s_src[warp][jn];
            ull xn = xgu[(size_t)sn * 32 + lane];
            ulonglong2 wA = *(const ulonglong2*)&s_wp[warp][j][0];
            ulonglong2 wB = *(const ulonglong2*)&s_wp[warp][j][2];
            acc0 = fma2(wA.x, xv, acc0);
            acc1 = fma2(wA.y, xv, acc1);
            acc2 = fma2(wB.x, xv, acc2);
            acc3 = fma2(wB.y, xv, acc3);
            xv = xn;
        }
        __syncwarp();
    }

    #pragma unroll
    for (int o = 16; o > 0; o >>= 1) {
        p0 += __shfl_xor_sync(0xffffffffu, p0, o);
        p1 += __shfl_xor_sync(0xffffffffu, p1, o);
        p2 += __shfl_xor_sync(0xffffffffu, p2, o);
        p3 += __shfl_xor_sync(0xffffffffu, p3, o);
    }
    float i0 = 1.0f / (p0 + ws0);
    float i1 = 1.0f / (p1 + ws1);
    float i2 = 1.0f / (p2 + ws2);
    float i3 = 1.0f / (p3 + ws3);

    float lo, hi;
    float* zp = g_z + ((size_t)g * N_ + dst) * HC_ + 2 * lane;
    unpack2(acc0, lo, hi); *(float2*)(zp +   0) = make_float2(lo * i0, hi * i0);
    unpack2(acc1, lo, hi); *(float2*)(zp +  64) = make_float2(lo * i1, hi * i1);
    unpack2(acc2, lo, hi); *(float2*)(zp + 128) = make_float2(lo * i2, hi * i2);
    unpack2(acc3, lo, hi); *(float2*)(zp + 192) = make_float2(lo * i3, hi * i3);
}

// ============================================================
// K3: out = z @ Wt + bias -> [B,Co,T,N].
// Conflict-free layouts: z staged as n-pair ulls [k][np];
// w staged as two split arrays (16B stride). Thread tile 8n x 4co.
// Block 128 (ng=tid>>4: 0..7, cg=tid&15: 0..15). grid (8, 96).
// ============================================================
#define KC 64
__global__ void __launch_bounds__(128) gemm2_kernel(const float* __restrict__ bias,
                                                    float* __restrict__ out) {
    // 48 KB exactly: s_zp 16KB + s_wA 16KB + s_wB 16KB; os overlays front 17.4KB... 
    // os needs 17408 <= 49152 total, overlays s_zp+start of s_wA after mainloop.
    __shared__ __align__(16) char sm[49152];
    ull        (*s_zp)[32] = (ull(*)[32])sm;                       // [k][np] n-pair packed (16384 B)
    ulonglong2 (*s_wA)[16] = (ulonglong2(*)[16])(sm + 16384);      // [k][cg] co 0,1 (16384 B)
    ulonglong2 (*s_wB)[16] = (ulonglong2(*)[16])(sm + 32768);      // [k][cg] co 2,3 (16384 B)
    float      (*os)[68]   = (float(*)[68])sm;                     // epilogue [co][n] (17408 B)

    int g  = blockIdx.y;
    int n0 = blockIdx.x * 64;
    int b  = g / T_;
    int t  = g - b * T_;
    int tid = threadIdx.x;
    int ng = tid >> 4;    // 0..7  -> n-pairs ng*4 .. ng*4+3 (rows ng*8..ng*8+7)
    int cg = tid & 15;    // 0..15 -> co cg*4 .. cg*4+3

    ull acc[4][4];        // [n-pair][co]; lo=row 2np, hi=row 2np+1 (complete outputs)
    #pragma unroll
    for (int i = 0; i < 4; i++)
        #pragma unroll
        for (int j = 0; j < 4; j++) acc[i][j] = 0ULL;

    const float* zrow = g_z + ((size_t)g * N_ + n0) * HC_;
    int np_s  = tid & 31;   // staging pair id
    int kq0_s = tid >> 5;   // 0..3

    for (int kk = 0; kk < 4; kk++) {
        __syncthreads();
        // stage z: pack n-pairs. s_zp[k][np] = (z[2np][k], z[2np+1][k])
        {
            const float* z0 = zrow + (size_t)(2 * np_s) * HC_ + kk * KC;
            const float* z1 = z0 + HC_;
            #pragma unroll
            for (int kq = kq0_s; kq < KC / 4; kq += 4) {
                float4 a = *(const float4*)(z0 + kq * 4);
                float4 c = *(const float4*)(z1 + kq * 4);
                s_zp[kq * 4 + 0][np_s] = pack2(a.x, c.x);
                s_zp[kq * 4 + 1][np_s] = pack2(a.y, c.y);
                s_zp[kq * 4 + 2][np_s] = pack2(a.z, c.z);
                s_zp[kq * 4 + 3][np_s] = pack2(a.w, c.w);
            }
        }
        // stage w: split even/odd ulonglong2 of each row
        #pragma unroll
        for (int i = tid; i < KC * 32; i += 128) {
            int k = i >> 5, j = i & 31;
            ulonglong2 v = *(const ulonglong2*)(g_Wdup + (size_t)(kk * KC + k) * CO_ + j * 2);
            if (j & 1) s_wB[k][j >> 1] = v;
            else       s_wA[k][j >> 1] = v;
        }
        __syncthreads();

        #pragma unroll 4
        for (int k = 0; k < KC; k++) {
            ulonglong2 zA = *(const ulonglong2*)&s_zp[k][ng * 4];      // pairs 0,1
            ulonglong2 zB = *(const ulonglong2*)&s_zp[k][ng * 4 + 2];  // pairs 2,3
            ulonglong2 wA = s_wA[k][cg];   // co 0,1 (dup)
            ulonglong2 wB = s_wB[k][cg];   // co 2,3 (dup)
            acc[0][0] = fma2(zA.x, wA.x, acc[0][0]);
            acc[0][1] = fma2(zA.x, wA.y, acc[0][1]);
            acc[0][2] = fma2(zA.x, wB.x, acc[0][2]);
            acc[0][3] = fma2(zA.x, wB.y, acc[0][3]);
            acc[1][0] = fma2(zA.y, wA.x, acc[1][0]);
            acc[1][1] = fma2(zA.y, wA.y, acc[1][1]);
            acc[1][2] = fma2(zA.y, wB.x, acc[1][2]);
            acc[1][3] = fma2(zA.y, wB.y, acc[1][3]);
            acc[2][0] = fma2(zB.x, wA.x, acc[2][0]);
            acc[2][1] = fma2(zB.x, wA.y, acc[2][1]);
            acc[2][2] = fma2(zB.x, wB.x, acc[2][2]);
            acc[2][3] = fma2(zB.x, wB.y, acc[2][3]);
            acc[3][0] = fma2(zB.y, wA.x, acc[3][0]);
            acc[3][1] = fma2(zB.y, wA.y, acc[3][1]);
            acc[3][2] = fma2(zB.y, wB.x, acc[3][2]);
            acc[3][3] = fma2(zB.y, wB.y, acc[3][3]);
        }
    }
    __syncthreads();   // mainloop smem dead; reuse as os[co][n]

    #pragma unroll
    for (int p = 0; p < 4; p++) {
        int n = ng * 8 + p * 2;
        #pragma unroll
        for (int j = 0; j < 4; j++) {
            float lo, hi;
            unpack2(acc[p][j], lo, hi);
            os[cg * 4 + j][n]     = lo;
            os[cg * 4 + j][n + 1] = hi;
        }
    }
    __syncthreads();

    #pragma unroll
    for (int i = tid; i < 64 * 16; i += 128) {
        int co = i >> 4, q = i & 15;
        float bv = __ldg(&bias[co]);
        float4 v = *(const float4*)&os[co][q * 4];
        v.x += bv; v.y += bv; v.z += bv; v.w += bv;
        *(float4*)(out + (((size_t)b * CO_ + co) * T_ + t) * N_ + n0 + q * 4) = v;
    }
}

// ============================================================
extern "C" void kernel_launch(void* const* d_in, const int* in_sizes, int n_in,
                              void* d_out, int out_size) {
    const float* x        = (const float*)d_in[0];
    const int*   ei       = (const int*)  d_in[1];
    const float* W        = (const float*)d_in[2];
    const float* att_src  = (const float*)d_in[3];
    const float* att_dst  = (const float*)d_in[4];
    const float* bias     = (const float*)d_in[5];
    float*       out      = (float*)d_out;
    int E = in_sizes[1] / 2;

    setup_kernel<<<2, 512>>>(ei, E, W, att_src, att_dst);
    xt_asrc_kernel<<<dim3(N_ / 128, G_), 256>>>(x);
    aggregate_kernel<<<dim3(N_ / 8, G_), 256>>>();
    gemm2_kernel<<<dim3(N_ / 64, G_), 128>>>(bias, out);
}

// round 9
// speedup vs baseline: 1.4621x; 1.0908x over previous
#include <cuda_runtime.h>
#include <cstdint>

#define B_  8
#define C_  64
#define T_  12
#define N_  512
#define G_  (B_ * T_)      // 96
#define H_  4
#define CO_ 64
#define HC_ (H_ * CO_)     // 256
#define NEG_SLOPE 0.2f
#define EMAX 16384

typedef unsigned long long ull;

// ---------------- device scratch ----------------
__device__ float g_xt[(size_t)G_ * N_ * C_];     // [G,N,64]
__device__ float g_z [(size_t)G_ * N_ * HC_];    // [G,N,256]
__device__ float g_asrc[(size_t)G_ * N_ * H_];   // [G,N,4]
__device__ float g_adst[(size_t)G_ * N_ * H_];
__device__ float g_u[2 * H_ * C_];               // [src/dst][h][c]
__device__ float g_Wt[HC_ * CO_];                // [k][co] = 0.25*W[c][h*64+co], k=h*64+c
__device__ int   g_rowptr[N_ + 1];
__device__ int   g_col[EMAX];

__device__ __forceinline__ float lrelu(float x) {
    return x > 0.0f ? x : NEG_SLOPE * x;
}
__device__ __forceinline__ ull pack2(float lo, float hi) {
    ull d;
    asm("mov.b64 %0, {%1, %2};" : "=l"(d) : "r"(__float_as_uint(lo)), "r"(__float_as_uint(hi)));
    return d;
}
__device__ __forceinline__ void unpack2(ull v, float& lo, float& hi) {
    unsigned a, b;
    asm("mov.b64 {%0, %1}, %2;" : "=r"(a), "=r"(b) : "l"(v));
    lo = __uint_as_float(a); hi = __uint_as_float(b);
}
__device__ __forceinline__ ull fma2(ull a, ull b, ull c) {
    ull d;
    asm("fma.rn.f32x2 %0, %1, %2, %3;" : "=l"(d) : "l"(a), "l"(b), "l"(c));
    return d;
}

// tf32 helpers
__device__ __forceinline__ void tf32_split(float v, unsigned& hi, unsigned& lo) {
    asm("cvt.rna.tf32.f32 %0, %1;" : "=r"(hi) : "f"(v));
    float r = v - __uint_as_float(hi);
    asm("cvt.rna.tf32.f32 %0, %1;" : "=r"(lo) : "f"(r));
}
__device__ __forceinline__ void mma_tf32(float& d0, float& d1, float& d2, float& d3,
                                         unsigned a0, unsigned a1, unsigned a2, unsigned a3,
                                         unsigned b0, unsigned b1) {
    asm volatile("mma.sync.aligned.m16n8k8.row.col.f32.tf32.tf32.f32 "
                 "{%0,%1,%2,%3}, {%4,%5,%6,%7}, {%8,%9}, {%0,%1,%2,%3};"
                 : "+f"(d0), "+f"(d1), "+f"(d2), "+f"(d3)
                 : "r"(a0), "r"(a1), "r"(a2), "r"(a3), "r"(b0), "r"(b1));
}

// ============================================================
// K0: setup. block 0: CSR build. block 1: prep u + Wt. 512 thr.
// ============================================================
__global__ void setup_kernel(const int* __restrict__ ei, int E,
                             const float* __restrict__ W,
                             const float* __restrict__ att_src,
                             const float* __restrict__ att_dst) {
    int tid = threadIdx.x;
    if (blockIdx.x == 0) {
        __shared__ int cnt[N_];
        __shared__ int cur[N_];
        __shared__ int wsum[16];
        cnt[tid] = 0;
        __syncthreads();
        const int* dst = ei + E;
        for (int e = tid; e < E; e += N_) atomicAdd(&cnt[dst[e]], 1);
        __syncthreads();

        int v = cnt[tid];
        int lane = tid & 31, wid = tid >> 5;
        int inc = v;
        #pragma unroll
        for (int o = 1; o < 32; o <<= 1) {
            int u = __shfl_up_sync(0xffffffffu, inc, o);
            if (lane >= o) inc += u;
        }
        if (lane == 31) wsum[wid] = inc;
        __syncthreads();
        if (wid == 0 && lane < 16) {
            int ws = wsum[lane];
            int wi = ws;
            #pragma unroll
            for (int o = 1; o < 16; o <<= 1) {
                int u = __shfl_up_sync(0x0000ffffu, wi, o);
                if (lane >= o) wi += u;
            }
            wsum[lane] = wi - ws;
        }
        __syncthreads();
        int excl = inc - v + wsum[wid];
        g_rowptr[tid] = excl;
        cur[tid] = excl;
        if (tid == N_ - 1) g_rowptr[N_] = excl + v;
        __syncthreads();

        for (int e = tid; e < E; e += N_) {
            int d = dst[e];
            int p = atomicAdd(&cur[d], 1);
            g_col[p] = ei[e];
        }
    } else {
        __shared__ float satt[2 * H_ * CO_];
        satt[tid] = (tid < 256) ? att_src[tid] : att_dst[tid - 256];
        __syncthreads();

        {
            int k = tid;                 // 512 = 2*4*64
            int p = k >> 8;
            int h = (k >> 6) & 3;
            int c = k & 63;
            const float* wrow = W + (size_t)c * HC_ + h * CO_;
            const float* av = satt + p * 256 + h * CO_;
            float s = 0.0f;
            #pragma unroll 16
            for (int co = 0; co < CO_; co++) s += wrow[co] * av[co];
            g_u[k] = s;
        }
        for (int idx = tid; idx < HC_ * CO_; idx += 512) {
            int k  = idx >> 6;
            int co = idx & 63;
            int h = k >> 6, c = k & 63;
            g_Wt[idx] = 0.25f * W[(size_t)c * HC_ + h * CO_ + co];
        }
    }
}

// ============================================================
// K1: per g: transpose x -> xt, asrc/adst = x . u
// grid (4, 96), block 256.
// ============================================================
__global__ void xt_asrc_kernel(const float* __restrict__ x) {
    __shared__ float xs[64][129];
    __shared__ float su[8][64];
    int g  = blockIdx.y;
    int n0 = blockIdx.x * 128;
    int b  = g / T_;
    int t  = g - b * T_;
    int tid = threadIdx.x;

    for (int i = tid; i < 512; i += 256) su[i >> 6][i & 63] = g_u[i];
    #pragma unroll
    for (int i = tid; i < 64 * 32; i += 256) {
        int c = i >> 5, q = i & 31;
        float4 v = *(const float4*)(x + (((size_t)b * C_ + c) * T_ + t) * N_ + n0 + q * 4);
        xs[c][q * 4 + 0] = v.x; xs[c][q * 4 + 1] = v.y;
        xs[c][q * 4 + 2] = v.z; xs[c][q * 4 + 3] = v.w;
    }
    __syncthreads();

    {
        int n = tid & 127;
        int p = tid >> 7;
        float a0 = 0.f, a1 = 0.f, a2 = 0.f, a3 = 0.f;
        #pragma unroll 16
        for (int c = 0; c < 64; c++) {
            float xv = xs[c][n];
            a0 = fmaf(xv, su[p * 4 + 0][c], a0);
            a1 = fmaf(xv, su[p * 4 + 1][c], a1);
            a2 = fmaf(xv, su[p * 4 + 2][c], a2);
            a3 = fmaf(xv, su[p * 4 + 3][c], a3);
        }
        float* dstp = (p == 0 ? g_asrc : g_adst) + ((size_t)g * N_ + n0 + n) * H_;
        dstp[0] = a0; dstp[1] = a1; dstp[2] = a2; dstp[3] = a3;
    }

    #pragma unroll
    for (int i = tid; i < 128 * 16; i += 256) {
        int n = i >> 4, q = i & 15;
        float4 v = {xs[q * 4 + 0][n], xs[q * 4 + 1][n], xs[q * 4 + 2][n], xs[q * 4 + 3][n]};
        *(float4*)(g_xt + ((size_t)g * N_ + n0 + n) * C_ + q * 4) = v;
    }
}

// ============================================================
// K2: aggregate in x-space, warp per (g,dst). (unchanged, proven)
// ============================================================
__global__ void __launch_bounds__(256) aggregate_kernel() {
    __shared__ float4 s_as[N_];
    __shared__ ull    s_wp[8][32][4];
    __shared__ int    s_src[8][32];
    int g    = blockIdx.y;
    int tid  = threadIdx.x;
    int warp = tid >> 5, lane = tid & 31;

    const float4* asrc_g = (const float4*)(g_asrc + (size_t)g * N_ * H_);
    for (int i = tid; i < N_; i += 256) s_as[i] = asrc_g[i];
    __syncthreads();

    int dst   = (blockIdx.x << 3) + warp;
    int start = g_rowptr[dst];
    int end   = g_rowptr[dst + 1];

    float4 ad = *(const float4*)(g_adst + ((size_t)g * N_ + dst) * H_);
    float4 sa = s_as[dst];
    float ws0 = __expf(lrelu(sa.x + ad.x));
    float ws1 = __expf(lrelu(sa.y + ad.y));
    float ws2 = __expf(lrelu(sa.z + ad.z));
    float ws3 = __expf(lrelu(sa.w + ad.w));

    const ull* xgu = (const ull*)(g_xt + (size_t)g * N_ * C_);

    ull xdv = xgu[(size_t)dst * 32 + lane];
    ull acc0 = fma2(pack2(ws0, ws0), xdv, 0ULL);
    ull acc1 = fma2(pack2(ws1, ws1), xdv, 0ULL);
    ull acc2 = fma2(pack2(ws2, ws2), xdv, 0ULL);
    ull acc3 = fma2(pack2(ws3, ws3), xdv, 0ULL);

    float p0 = 0.f, p1 = 0.f, p2 = 0.f, p3 = 0.f;

    for (int base = start; base < end; base += 32) {
        int e = base + lane;
        int src = 0;
        float w0 = 0.f, w1 = 0.f, w2 = 0.f, w3 = 0.f;
        if (e < end) {
            src = g_col[e];
            float4 a = s_as[src];
            w0 = __expf(lrelu(a.x + ad.x));
            w1 = __expf(lrelu(a.y + ad.y));
            w2 = __expf(lrelu(a.z + ad.z));
            w3 = __expf(lrelu(a.w + ad.w));
        }
        p0 += w0; p1 += w1; p2 += w2; p3 += w3;
        ulonglong2 pA, pB;
        pA.x = pack2(w0, w0); pA.y = pack2(w1, w1);
        pB.x = pack2(w2, w2); pB.y = pack2(w3, w3);
        *(ulonglong2*)&s_wp[warp][lane][0] = pA;
        *(ulonglong2*)&s_wp[warp][lane][2] = pB;
        s_src[warp][lane] = src;
        __syncwarp();

        int cnt = min(32, end - base);
        int sj = s_src[warp][0];
        ull xv = xgu[(size_t)sj * 32 + lane];
        for (int j = 0; j < cnt; j++) {
            int jn = min(j + 1, cnt - 1);
            int sn = s_src[warp][jn];
            ull xn = xgu[(size_t)sn * 32 + lane];
            ulonglong2 wA = *(const ulonglong2*)&s_wp[warp][j][0];
            ulonglong2 wB = *(const ulonglong2*)&s_wp[warp][j][2];
            acc0 = fma2(wA.x, xv, acc0);
            acc1 = fma2(wA.y, xv, acc1);
            acc2 = fma2(wB.x, xv, acc2);
            acc3 = fma2(wB.y, xv, acc3);
            xv = xn;
        }
        __syncwarp();
    }

    #pragma unroll
    for (int o = 16; o > 0; o >>= 1) {
        p0 += __shfl_xor_sync(0xffffffffu, p0, o);
        p1 += __shfl_xor_sync(0xffffffffu, p1, o);
        p2 += __shfl_xor_sync(0xffffffffu, p2, o);
        p3 += __shfl_xor_sync(0xffffffffu, p3, o);
    }
    float i0 = 1.0f / (p0 + ws0);
    float i1 = 1.0f / (p1 + ws1);
    float i2 = 1.0f / (p2 + ws2);
    float i3 = 1.0f / (p3 + ws3);

    float lo, hi;
    float* zp = g_z + ((size_t)g * N_ + dst) * HC_ + 2 * lane;
    unpack2(acc0, lo, hi); *(float2*)(zp +   0) = make_float2(lo * i0, hi * i0);
    unpack2(acc1, lo, hi); *(float2*)(zp +  64) = make_float2(lo * i1, hi * i1);
    unpack2(acc2, lo, hi); *(float2*)(zp + 128) = make_float2(lo * i2, hi * i2);
    unpack2(acc3, lo, hi); *(float2*)(zp + 192) = make_float2(lo * i3, hi * i3);
}

// ============================================================
// K3: out = z @ Wt + bias -> [B,Co,T,N], tensor cores (tf32 3-term).
// CTA: 256 thr (8 warps), tile 256 n x 64 co, K chunks of 32.
// Warp: 32 n (2 m16 tiles) x 64 co (8 n8 tiles). grid (2, 96).
// ============================================================
__global__ void __launch_bounds__(256) gemm2_tc_kernel(const float* __restrict__ bias,
                                                       float* __restrict__ out) {
    __shared__ float s_z[256][36];   // [n][k] chunk, pitch 36: A-frag loads conflict-free
    __shared__ float s_w[32][72];    // [k][co] chunk, pitch 72: B-frag loads conflict-free

    int g    = blockIdx.y;
    int half = blockIdx.x;
    int b    = g / T_;
    int t    = g - b * T_;
    int tid  = threadIdx.x;
    int w    = tid >> 5;
    int lane = tid & 31;
    int gid  = lane >> 2;   // 0..7
    int tig  = lane & 3;    // 0..3

    float acc[2][8][4];
    #pragma unroll
    for (int mt = 0; mt < 2; mt++)
        #pragma unroll
        for (int ct = 0; ct < 8; ct++)
            #pragma unroll
            for (int j = 0; j < 4; j++) acc[mt][ct][j] = 0.0f;

    const float* zrow = g_z + ((size_t)g * N_ + half * 256) * HC_;

    for (int kk = 0; kk < 8; kk++) {
        __syncthreads();
        // stage z chunk [256 n][32 k]
        #pragma unroll
        for (int i = tid; i < 2048; i += 256) {
            int n = i >> 3, q = i & 7;
            *(float4*)&s_z[n][q * 4] = *(const float4*)(zrow + (size_t)n * HC_ + kk * 32 + q * 4);
        }
        // stage w chunk [32 k][64 co]
        #pragma unroll
        for (int i = tid; i < 512; i += 256) {
            int k = i >> 4, q = i & 15;
            *(float4*)&s_w[k][q * 4] = *(const float4*)(g_Wt + (size_t)(kk * 32 + k) * CO_ + q * 4);
        }
        __syncthreads();

        #pragma unroll
        for (int q = 0; q < 4; q++) {
            int k0 = q * 8;
            unsigned ah[2][4], al[2][4];
            #pragma unroll
            for (int mt = 0; mt < 2; mt++) {
                int rb = w * 32 + mt * 16 + gid;
                tf32_split(s_z[rb    ][k0 + tig    ], ah[mt][0], al[mt][0]);
                tf32_split(s_z[rb + 8][k0 + tig    ], ah[mt][1], al[mt][1]);
                tf32_split(s_z[rb    ][k0 + tig + 4], ah[mt][2], al[mt][2]);
                tf32_split(s_z[rb + 8][k0 + tig + 4], ah[mt][3], al[mt][3]);
            }
            #pragma unroll
            for (int ct = 0; ct < 8; ct++) {
                unsigned bh0, bl0, bh1, bl1;
                int co = ct * 8 + gid;
                tf32_split(s_w[k0 + tig    ][co], bh0, bl0);
                tf32_split(s_w[k0 + tig + 4][co], bh1, bl1);
                #pragma unroll
                for (int mt = 0; mt < 2; mt++) {
                    mma_tf32(acc[mt][ct][0], acc[mt][ct][1], acc[mt][ct][2], acc[mt][ct][3],
                             ah[mt][0], ah[mt][1], ah[mt][2], ah[mt][3], bh0, bh1);
                    mma_tf32(acc[mt][ct][0], acc[mt][ct][1], acc[mt][ct][2], acc[mt][ct][3],
                             al[mt][0], al[mt][1], al[mt][2], al[mt][3], bh0, bh1);
                    mma_tf32(acc[mt][ct][0], acc[mt][ct][1], acc[mt][ct][2], acc[mt][ct][3],
                             ah[mt][0], ah[mt][1], ah[mt][2], ah[mt][3], bl0, bl1);
                }
            }
        }
    }

    // epilogue: direct STG with bias
    int n_base = half * 256 + w * 32;
    #pragma unroll
    for (int mt = 0; mt < 2; mt++) {
        int n_g = n_base + mt * 16 + gid;
        #pragma unroll
        for (int ct = 0; ct < 8; ct++) {
            int co = ct * 8 + 2 * tig;
            float bv0 = __ldg(&bias[co]);
            float bv1 = __ldg(&bias[co + 1]);
            float* o0 = out + (((size_t)b * CO_ + co)     * T_ + t) * N_ + n_g;
            float* o1 = out + (((size_t)b * CO_ + co + 1) * T_ + t) * N_ + n_g;
            o0[0] = acc[mt][ct][0] + bv0;
            o1[0] = acc[mt][ct][1] + bv1;
            o0[8] = acc[mt][ct][2] + bv0;
            o1[8] = acc[mt][ct][3] + bv1;
        }
    }
}

// ============================================================
extern "C" void kernel_launch(void* const* d_in, const int* in_sizes, int n_in,
                              void* d_out, int out_size) {
    const float* x        = (const float*)d_in[0];
    const int*   ei       = (const int*)  d_in[1];
    const float* W        = (const float*)d_in[2];
    const float* att_src  = (const float*)d_in[3];
    const float* att_dst  = (const float*)d_in[4];
    const float* bias     = (const float*)d_in[5];
    float*       out      = (float*)d_out;
    int E = in_sizes[1] / 2;

    setup_kernel<<<2, 512>>>(ei, E, W, att_src, att_dst);
    xt_asrc_kernel<<<dim3(N_ / 128, G_), 256>>>(x);
    aggregate_kernel<<<dim3(N_ / 8, G_), 256>>>();
    gemm2_tc_kernel<<<dim3(2, G_), 256>>>(bias, out);
}

// round 11
// speedup vs baseline: 1.4842x; 1.0151x over previous
#include <cuda_runtime.h>
#include <cstdint>

#define B_  8
#define C_  64
#define T_  12
#define N_  512
#define G_  (B_ * T_)      // 96
#define H_  4
#define CO_ 64
#define HC_ (H_ * CO_)     // 256
#define NEG_SLOPE 0.2f
#define EMAX 16384

typedef unsigned long long ull;

// ---------------- device scratch ----------------
__device__ float    g_xt[(size_t)G_ * N_ * C_];    // [G,N,64]
__device__ unsigned g_zh[(size_t)G_ * N_ * HC_];   // [G,N,256] z tf32-hi
__device__ unsigned g_zl[(size_t)G_ * N_ * HC_];   // [G,N,256] z tf32-lo
__device__ float    g_asrc[(size_t)G_ * N_ * H_];  // [G,N,4]
__device__ float    g_adst[(size_t)G_ * N_ * H_];
__device__ float    g_u[2 * H_ * C_];              // [src/dst][h][c]
__device__ unsigned g_Wth[HC_ * CO_];              // [k][co] tf32-hi of 0.25*W
__device__ unsigned g_Wtl[HC_ * CO_];              // [k][co] tf32-lo
__device__ int      g_rowptr[N_ + 1];
__device__ int      g_col[EMAX];

__device__ __forceinline__ float lrelu(float x) {
    return x > 0.0f ? x : NEG_SLOPE * x;
}
__device__ __forceinline__ ull pack2(float lo, float hi) {
    ull d;
    asm("mov.b64 %0, {%1, %2};" : "=l"(d) : "r"(__float_as_uint(lo)), "r"(__float_as_uint(hi)));
    return d;
}
__device__ __forceinline__ void unpack2(ull v, float& lo, float& hi) {
    unsigned a, b;
    asm("mov.b64 {%0, %1}, %2;" : "=r"(a), "=r"(b) : "l"(v));
    lo = __uint_as_float(a); hi = __uint_as_float(b);
}
__device__ __forceinline__ ull fma2(ull a, ull b, ull c) {
    ull d;
    asm("fma.rn.f32x2 %0, %1, %2, %3;" : "=l"(d) : "l"(a), "l"(b), "l"(c));
    return d;
}
__device__ __forceinline__ void tf32_split(float v, unsigned& hi, unsigned& lo) {
    asm("cvt.rna.tf32.f32 %0, %1;" : "=r"(hi) : "f"(v));
    float r = v - __uint_as_float(hi);
    asm("cvt.rna.tf32.f32 %0, %1;" : "=r"(lo) : "f"(r));
}
__device__ __forceinline__ void mma_tf32(float& d0, float& d1, float& d2, float& d3,
                                         unsigned a0, unsigned a1, unsigned a2, unsigned a3,
                                         unsigned b0, unsigned b1) {
    asm volatile("mma.sync.aligned.m16n8k8.row.col.f32.tf32.tf32.f32 "
                 "{%0,%1,%2,%3}, {%4,%5,%6,%7}, {%8,%9}, {%0,%1,%2,%3};"
                 : "+f"(d0), "+f"(d1), "+f"(d2), "+f"(d3)
                 : "r"(a0), "r"(a1), "r"(a2), "r"(a3), "r"(b0), "r"(b1));
}

// ============================================================
// K0: setup. block 0: CSR build. block 1: prep u + Wt splits. 512 thr.
// ============================================================
__global__ void setup_kernel(const int* __restrict__ ei, int E,
                             const float* __restrict__ W,
                             const float* __restrict__ att_src,
                             const float* __restrict__ att_dst) {
    int tid = threadIdx.x;
    if (blockIdx.x == 0) {
        __shared__ int cnt[N_];
        __shared__ int cur[N_];
        __shared__ int wsum[16];
        cnt[tid] = 0;
        __syncthreads();
        const int* dst = ei + E;
        for (int e = tid; e < E; e += N_) atomicAdd(&cnt[dst[e]], 1);
        __syncthreads();

        int v = cnt[tid];
        int lane = tid & 31, wid = tid >> 5;
        int inc = v;
        #pragma unroll
        for (int o = 1; o < 32; o <<= 1) {
            int u = __shfl_up_sync(0xffffffffu, inc, o);
            if (lane >= o) inc += u;
        }
        if (lane == 31) wsum[wid] = inc;
        __syncthreads();
        if (wid == 0 && lane < 16) {
            int ws = wsum[lane];
            int wi = ws;
            #pragma unroll
            for (int o = 1; o < 16; o <<= 1) {
                int u = __shfl_up_sync(0x0000ffffu, wi, o);
                if (lane >= o) wi += u;
            }
            wsum[lane] = wi - ws;
        }
        __syncthreads();
        int excl = inc - v + wsum[wid];
        g_rowptr[tid] = excl;
        cur[tid] = excl;
        if (tid == N_ - 1) g_rowptr[N_] = excl + v;
        __syncthreads();

        for (int e = tid; e < E; e += N_) {
            int d = dst[e];
            int p = atomicAdd(&cur[d], 1);
            g_col[p] = ei[e];
        }
    } else {
        __shared__ float satt[2 * H_ * CO_];
        satt[tid] = (tid < 256) ? att_src[tid] : att_dst[tid - 256];
        __syncthreads();

        {
            int k = tid;                 // 512 = 2*4*64
            int p = k >> 8;
            int h = (k >> 6) & 3;
            int c = k & 63;
            const float* wrow = W + (size_t)c * HC_ + h * CO_;
            const float* av = satt + p * 256 + h * CO_;
            float s = 0.0f;
            #pragma unroll 16
            for (int co = 0; co < CO_; co++) s += wrow[co] * av[co];
            g_u[k] = s;
        }
        // Wt splits: wt = 0.25*W[c][h*64+co], k=h*64+c
        for (int idx = tid; idx < HC_ * CO_; idx += 512) {
            int k  = idx >> 6;
            int co = idx & 63;
            int h = k >> 6, c = k & 63;
            float wt = 0.25f * W[(size_t)c * HC_ + h * CO_ + co];
            unsigned whi, wlo;
            tf32_split(wt, whi, wlo);
            g_Wth[idx] = whi;
            g_Wtl[idx] = wlo;
        }
    }
}

// ============================================================
// K1: per g: transpose x -> xt, asrc/adst = x . u
// grid (4, 96), block 256.
// ============================================================
__global__ void xt_asrc_kernel(const float* __restrict__ x) {
    __shared__ float xs[64][129];
    __shared__ float su[8][64];
    int g  = blockIdx.y;
    int n0 = blockIdx.x * 128;
    int b  = g / T_;
    int t  = g - b * T_;
    int tid = threadIdx.x;

    for (int i = tid; i < 512; i += 256) su[i >> 6][i & 63] = g_u[i];
    #pragma unroll
    for (int i = tid; i < 64 * 32; i += 256) {
        int c = i >> 5, q = i & 31;
        float4 v = *(const float4*)(x + (((size_t)b * C_ + c) * T_ + t) * N_ + n0 + q * 4);
        xs[c][q * 4 + 0] = v.x; xs[c][q * 4 + 1] = v.y;
        xs[c][q * 4 + 2] = v.z; xs[c][q * 4 + 3] = v.w;
    }
    __syncthreads();

    {
        int n = tid & 127;
        int p = tid >> 7;
        float a0 = 0.f, a1 = 0.f, a2 = 0.f, a3 = 0.f;
        #pragma unroll 16
        for (int c = 0; c < 64; c++) {
            float xv = xs[c][n];
            a0 = fmaf(xv, su[p * 4 + 0][c], a0);
            a1 = fmaf(xv, su[p * 4 + 1][c], a1);
            a2 = fmaf(xv, su[p * 4 + 2][c], a2);
            a3 = fmaf(xv, su[p * 4 + 3][c], a3);
        }
        float* dstp = (p == 0 ? g_asrc : g_adst) + ((size_t)g * N_ + n0 + n) * H_;
        dstp[0] = a0; dstp[1] = a1; dstp[2] = a2; dstp[3] = a3;
    }

    #pragma unroll
    for (int i = tid; i < 128 * 16; i += 256) {
        int n = i >> 4, q = i & 15;
        float4 v = {xs[q * 4 + 0][n], xs[q * 4 + 1][n], xs[q * 4 + 2][n], xs[q * 4 + 3][n]};
        *(float4*)(g_xt + ((size_t)g * N_ + n0 + n) * C_ + q * 4) = v;
    }
}

// ============================================================
// K2: aggregate in x-space, warp per (g,dst). Core unchanged;
// epilogue writes tf32 hi/lo splits of z.
// ============================================================
__global__ void __launch_bounds__(256) aggregate_kernel() {
    __shared__ float4 s_as[N_];
    __shared__ ull    s_wp[8][32][4];
    __shared__ int    s_src[8][32];
    int g    = blockIdx.y;
    int tid  = threadIdx.x;
    int warp = tid >> 5, lane = tid & 31;

    const float4* asrc_g = (const float4*)(g_asrc + (size_t)g * N_ * H_);
    for (int i = tid; i < N_; i += 256) s_as[i] = asrc_g[i];
    __syncthreads();

    int dst   = (blockIdx.x << 3) + warp;
    int start = g_rowptr[dst];
    int end   = g_rowptr[dst + 1];

    float4 ad = *(const float4*)(g_adst + ((size_t)g * N_ + dst) * H_);
    float4 sa = s_as[dst];
    float ws0 = __expf(lrelu(sa.x + ad.x));
    float ws1 = __expf(lrelu(sa.y + ad.y));
    float ws2 = __expf(lrelu(sa.z + ad.z));
    float ws3 = __expf(lrelu(sa.w + ad.w));

    const ull* xgu = (const ull*)(g_xt + (size_t)g * N_ * C_);

    ull xdv = xgu[(size_t)dst * 32 + lane];
    ull acc0 = fma2(pack2(ws0, ws0), xdv, 0ULL);
    ull acc1 = fma2(pack2(ws1, ws1), xdv, 0ULL);
    ull acc2 = fma2(pack2(ws2, ws2), xdv, 0ULL);
    ull acc3 = fma2(pack2(ws3, ws3), xdv, 0ULL);

    float p0 = 0.f, p1 = 0.f, p2 = 0.f, p3 = 0.f;

    for (int base = start; base < end; base += 32) {
        int e = base + lane;
        int src = 0;
        float w0 = 0.f, w1 = 0.f, w2 = 0.f, w3 = 0.f;
        if (e < end) {
            src = g_col[e];
            float4 a = s_as[src];
            w0 = __expf(lrelu(a.x + ad.x));
            w1 = __expf(lrelu(a.y + ad.y));
            w2 = __expf(lrelu(a.z + ad.z));
            w3 = __expf(lrelu(a.w + ad.w));
        }
        p0 += w0; p1 += w1; p2 += w2; p3 += w3;
        ulonglong2 pA, pB;
        pA.x = pack2(w0, w0); pA.y = pack2(w1, w1);
        pB.x = pack2(w2, w2); pB.y = pack2(w3, w3);
        *(ulonglong2*)&s_wp[warp][lane][0] = pA;
        *(ulonglong2*)&s_wp[warp][lane][2] = pB;
        s_src[warp][lane] = src;
        __syncwarp();

        int cnt = min(32, end - base);
        int sj = s_src[warp][0];
        ull xv = xgu[(size_t)sj * 32 + lane];
        for (int j = 0; j < cnt; j++) {
            int jn = min(j + 1, cnt - 1);
            int sn = s_src[warp][jn];
            ull xn = xgu[(size_t)sn * 32 + lane];
            ulonglong2 wA = *(const ulonglong2*)&s_wp[warp][j][0];
            ulonglong2 wB = *(const ulonglong2*)&s_wp[warp][j][2];
            acc0 = fma2(wA.x, xv, acc0);
            acc1 = fma2(wA.y, xv, acc1);
            acc2 = fma2(wB.x, xv, acc2);
            acc3 = fma2(wB.y, xv, acc3);
            xv = xn;
        }
        __syncwarp();
    }

    #pragma unroll
    for (int o = 16; o > 0; o >>= 1) {
        p0 += __shfl_xor_sync(0xffffffffu, p0, o);
        p1 += __shfl_xor_sync(0xffffffffu, p1, o);
        p2 += __shfl_xor_sync(0xffffffffu, p2, o);
        p3 += __shfl_xor_sync(0xffffffffu, p3, o);
    }
    float i0 = 1.0f / (p0 + ws0);
    float i1 = 1.0f / (p1 + ws1);
    float i2 = 1.0f / (p2 + ws2);
    float i3 = 1.0f / (p3 + ws3);

    // epilogue: split z into tf32 hi/lo and store both
    size_t zoff = ((size_t)g * N_ + dst) * HC_ + 2 * lane;
    unsigned* zph = g_zh + zoff;
    unsigned* zpl = g_zl + zoff;
    float lo, hi;
    uint2 vh, vl;
    unpack2(acc0, lo, hi); lo *= i0; hi *= i0;
    tf32_split(lo, vh.x, vl.x); tf32_split(hi, vh.y, vl.y);
    *(uint2*)(zph +   0) = vh; *(uint2*)(zpl +   0) = vl;
    unpack2(acc1, lo, hi); lo *= i1; hi *= i1;
    tf32_split(lo, vh.x, vl.x); tf32_split(hi, vh.y, vl.y);
    *(uint2*)(zph +  64) = vh; *(uint2*)(zpl +  64) = vl;
    unpack2(acc2, lo, hi); lo *= i2; hi *= i2;
    tf32_split(lo, vh.x, vl.x); tf32_split(hi, vh.y, vl.y);
    *(uint2*)(zph + 128) = vh; *(uint2*)(zpl + 128) = vl;
    unpack2(acc3, lo, hi); lo *= i3; hi *= i3;
    tf32_split(lo, vh.x, vl.x); tf32_split(hi, vh.y, vl.y);
    *(uint2*)(zph + 192) = vh; *(uint2*)(zpl + 192) = vl;
}

// ============================================================
// K3: out = z @ Wt + bias -> [B,Co,T,N], tensor cores, presplit operands.
// CTA 256 thr (8 warps), tile 128n x 64co; warp: 16n x 64co.
// K chunks of 16 (2 m16n8k8 steps). grid (4, 96) = 384 blocks.
// w pitch 72 (>=64 cols; 72%32=8 -> B-frag loads conflict-free).
// ============================================================
#define KCH 16
__global__ void __launch_bounds__(256) gemm2_tc_kernel(const float* __restrict__ bias,
                                                       float* __restrict__ out) {
    __shared__ unsigned s_zh[128][20];   // [n][k] pitch 20: conflict-free A frags
    __shared__ unsigned s_zl[128][20];
    __shared__ unsigned s_wh[KCH][72];   // [k][co] pitch 72: conflict-free B frags
    __shared__ unsigned s_wl[KCH][72];

    int g   = blockIdx.y;
    int qt  = blockIdx.x;          // n-quarter
    int b   = g / T_;
    int t   = g - b * T_;
    int tid = threadIdx.x;
    int w    = tid >> 5;
    int lane = tid & 31;
    int gid  = lane >> 2;   // 0..7
    int tig  = lane & 3;    // 0..3

    float acc[8][4];
    #pragma unroll
    for (int ct = 0; ct < 8; ct++)
        #pragma unroll
        for (int j = 0; j < 4; j++) acc[ct][j] = 0.0f;

    const unsigned* zh = g_zh + ((size_t)g * N_ + qt * 128) * HC_;
    const unsigned* zl = g_zl + ((size_t)g * N_ + qt * 128) * HC_;

    for (int kk = 0; kk < HC_ / KCH; kk++) {
        __syncthreads();
        // stage z chunk [128 n][16 k] hi+lo  (512 uint4 each)
        #pragma unroll
        for (int i = tid; i < 512; i += 256) {
            int n = i >> 2, q4 = i & 3;
            *(uint4*)&s_zh[n][q4 * 4] = *(const uint4*)(zh + (size_t)n * HC_ + kk * KCH + q4 * 4);
            *(uint4*)&s_zl[n][q4 * 4] = *(const uint4*)(zl + (size_t)n * HC_ + kk * KCH + q4 * 4);
        }
        // stage w chunk [16 k][64 co] hi+lo  (1 uint4 each per thread)
        {
            int k = tid >> 4, q4 = tid & 15;
            *(uint4*)&s_wh[k][q4 * 4] = *(const uint4*)(g_Wth + (size_t)(kk * KCH + k) * CO_ + q4 * 4);
            *(uint4*)&s_wl[k][q4 * 4] = *(const uint4*)(g_Wtl + (size_t)(kk * KCH + k) * CO_ + q4 * 4);
        }
        __syncthreads();

        #pragma unroll
        for (int q = 0; q < 2; q++) {
            int k0 = q * 8;
            int rb = w * 16 + gid;
            unsigned ah0 = s_zh[rb    ][k0 + tig    ];
            unsigned ah1 = s_zh[rb + 8][k0 + tig    ];
            unsigned ah2 = s_zh[rb    ][k0 + tig + 4];
            unsigned ah3 = s_zh[rb + 8][k0 + tig + 4];
            unsigned al0 = s_zl[rb    ][k0 + tig    ];
            unsigned al1 = s_zl[rb + 8][k0 + tig    ];
            unsigned al2 = s_zl[rb    ][k0 + tig + 4];
            unsigned al3 = s_zl[rb + 8][k0 + tig + 4];
            #pragma unroll
            for (int ct = 0; ct < 8; ct++) {
                int co = ct * 8 + gid;
                unsigned bh0 = s_wh[k0 + tig    ][co];
                unsigned bh1 = s_wh[k0 + tig + 4][co];
                unsigned bl0 = s_wl[k0 + tig    ][co];
                unsigned bl1 = s_wl[k0 + tig + 4][co];
                mma_tf32(acc[ct][0], acc[ct][1], acc[ct][2], acc[ct][3],
                         ah0, ah1, ah2, ah3, bh0, bh1);
                mma_tf32(acc[ct][0], acc[ct][1], acc[ct][2], acc[ct][3],
                         al0, al1, al2, al3, bh0, bh1);
                mma_tf32(acc[ct][0], acc[ct][1], acc[ct][2], acc[ct][3],
                         ah0, ah1, ah2, ah3, bl0, bl1);
            }
        }
    }

    // epilogue: direct STG with bias
    int n_g = qt * 128 + w * 16 + gid;
    #pragma unroll
    for (int ct = 0; ct < 8; ct++) {
        int co = ct * 8 + 2 * tig;
        float bv0 = __ldg(&bias[co]);
        float bv1 = __ldg(&bias[co + 1]);
        float* o0 = out + (((size_t)b * CO_ + co)     * T_ + t) * N_ + n_g;
        float* o1 = out + (((size_t)b * CO_ + co + 1) * T_ + t) * N_ + n_g;
        o0[0] = acc[ct][0] + bv0;
        o1[0] = acc[ct][1] + bv1;
        o0[8] = acc[ct][2] + bv0;
        o1[8] = acc[ct][3] + bv1;
    }
}

// ============================================================
extern "C" void kernel_launch(void* const* d_in, const int* in_sizes, int n_in,
                              void* d_out, int out_size) {
    const float* x        = (const float*)d_in[0];
    const int*   ei       = (const int*)  d_in[1];
    const float* W        = (const float*)d_in[2];
    const float* att_src  = (const float*)d_in[3];
    const float* att_dst  = (const float*)d_in[4];
    const float* bias     = (const float*)d_in[5];
    float*       out      = (float*)d_out;
    int E = in_sizes[1] / 2;

    setup_kernel<<<2, 512>>>(ei, E, W, att_src, att_dst);
    xt_asrc_kernel<<<dim3(N_ / 128, G_), 256>>>(x);
    aggregate_kernel<<<dim3(N_ / 8, G_), 256>>>();
    gemm2_tc_kernel<<<dim3(N_ / 128, G_), 256>>>(bias, out);
}

// round 12
// speedup vs baseline: 1.6149x; 1.0881x over previous
#include <cuda_runtime.h>
#include <cstdint>

#define B_  8
#define C_  64
#define T_  12
#define N_  512
#define G_  (B_ * T_)      // 96
#define H_  4
#define CO_ 64
#define HC_ (H_ * CO_)     // 256
#define NEG_SLOPE 0.2f
#define EMAX 16384

typedef unsigned long long ull;

// ---------------- device scratch ----------------
__device__ float    g_xt[(size_t)G_ * N_ * C_];    // [G,N,64]
__device__ float    g_z [(size_t)G_ * N_ * HC_];   // [G,N,256] fp32
__device__ float    g_asrc[(size_t)G_ * N_ * H_];  // [G,N,4]
__device__ float    g_adst[(size_t)G_ * N_ * H_];
__device__ float    g_u[2 * H_ * C_];              // [src/dst][h][c]
__device__ unsigned g_Wth[HC_ * CO_];              // [k][co] tf32-hi of 0.25*W
__device__ unsigned g_Wtl[HC_ * CO_];              // [k][co] tf32-lo
__device__ int      g_rowptr[N_ + 1];
__device__ int      g_col[EMAX];

__device__ __forceinline__ float lrelu(float x) {
    return x > 0.0f ? x : NEG_SLOPE * x;
}
__device__ __forceinline__ ull pack2(float lo, float hi) {
    ull d;
    asm("mov.b64 %0, {%1, %2};" : "=l"(d) : "r"(__float_as_uint(lo)), "r"(__float_as_uint(hi)));
    return d;
}
__device__ __forceinline__ void unpack2(ull v, float& lo, float& hi) {
    unsigned a, b;
    asm("mov.b64 {%0, %1}, %2;" : "=r"(a), "=r"(b) : "l"(v));
    lo = __uint_as_float(a); hi = __uint_as_float(b);
}
__device__ __forceinline__ ull fma2(ull a, ull b, ull c) {
    ull d;
    asm("fma.rn.f32x2 %0, %1, %2, %3;" : "=l"(d) : "l"(a), "l"(b), "l"(c));
    return d;
}
__device__ __forceinline__ void tf32_split(float v, unsigned& hi, unsigned& lo) {
    asm("cvt.rna.tf32.f32 %0, %1;" : "=r"(hi) : "f"(v));
    float r = v - __uint_as_float(hi);
    asm("cvt.rna.tf32.f32 %0, %1;" : "=r"(lo) : "f"(r));
}
__device__ __forceinline__ void mma_tf32(float& d0, float& d1, float& d2, float& d3,
                                         unsigned a0, unsigned a1, unsigned a2, unsigned a3,
                                         unsigned b0, unsigned b1) {
    asm volatile("mma.sync.aligned.m16n8k8.row.col.f32.tf32.tf32.f32 "
                 "{%0,%1,%2,%3}, {%4,%5,%6,%7}, {%8,%9}, {%0,%1,%2,%3};"
                 : "+f"(d0), "+f"(d1), "+f"(d2), "+f"(d3)
                 : "r"(a0), "r"(a1), "r"(a2), "r"(a3), "r"(b0), "r"(b1));
}

// ============================================================
// K0: setup. block 0: CSR build. block 1: prep u + Wt splits. 512 thr.
// ============================================================
__global__ void setup_kernel(const int* __restrict__ ei, int E,
                             const float* __restrict__ W,
                             const float* __restrict__ att_src,
                             const float* __restrict__ att_dst) {
    int tid = threadIdx.x;
    if (blockIdx.x == 0) {
        __shared__ int cnt[N_];
        __shared__ int cur[N_];
        __shared__ int wsum[16];
        cnt[tid] = 0;
        __syncthreads();
        const int* dst = ei + E;
        for (int e = tid; e < E; e += N_) atomicAdd(&cnt[dst[e]], 1);
        __syncthreads();

        int v = cnt[tid];
        int lane = tid & 31, wid = tid >> 5;
        int inc = v;
        #pragma unroll
        for (int o = 1; o < 32; o <<= 1) {
            int u = __shfl_up_sync(0xffffffffu, inc, o);
            if (lane >= o) inc += u;
        }
        if (lane == 31) wsum[wid] = inc;
        __syncthreads();
        if (wid == 0 && lane < 16) {
            int ws = wsum[lane];
            int wi = ws;
            #pragma unroll
            for (int o = 1; o < 16; o <<= 1) {
                int u = __shfl_up_sync(0x0000ffffu, wi, o);
                if (lane >= o) wi += u;
            }
            wsum[lane] = wi - ws;
        }
        __syncthreads();
        int excl = inc - v + wsum[wid];
        g_rowptr[tid] = excl;
        cur[tid] = excl;
        if (tid == N_ - 1) g_rowptr[N_] = excl + v;
        __syncthreads();

        for (int e = tid; e < E; e += N_) {
            int d = dst[e];
            int p = atomicAdd(&cur[d], 1);
            g_col[p] = ei[e];
        }
    } else {
        __shared__ float satt[2 * H_ * CO_];
        satt[tid] = (tid < 256) ? att_src[tid] : att_dst[tid - 256];
        __syncthreads();

        {
            int k = tid;                 // 512 = 2*4*64
            int p = k >> 8;
            int h = (k >> 6) & 3;
            int c = k & 63;
            const float* wrow = W + (size_t)c * HC_ + h * CO_;
            const float* av = satt + p * 256 + h * CO_;
            float s = 0.0f;
            #pragma unroll 16
            for (int co = 0; co < CO_; co++) s += wrow[co] * av[co];
            g_u[k] = s;
        }
        // Wt splits: wt = 0.25*W[c][h*64+co], k=h*64+c
        for (int idx = tid; idx < HC_ * CO_; idx += 512) {
            int k  = idx >> 6;
            int co = idx & 63;
            int h = k >> 6, c = k & 63;
            float wt = 0.25f * W[(size_t)c * HC_ + h * CO_ + co];
            unsigned whi, wlo;
            tf32_split(wt, whi, wlo);
            g_Wth[idx] = whi;
            g_Wtl[idx] = wlo;
        }
    }
}

// ============================================================
// K1: per g: transpose x -> xt, asrc/adst = x . u
// grid (4, 96), block 256.
// ============================================================
__global__ void xt_asrc_kernel(const float* __restrict__ x) {
    __shared__ float xs[64][129];
    __shared__ float su[8][64];
    int g  = blockIdx.y;
    int n0 = blockIdx.x * 128;
    int b  = g / T_;
    int t  = g - b * T_;
    int tid = threadIdx.x;

    for (int i = tid; i < 512; i += 256) su[i >> 6][i & 63] = g_u[i];
    #pragma unroll
    for (int i = tid; i < 64 * 32; i += 256) {
        int c = i >> 5, q = i & 31;
        float4 v = *(const float4*)(x + (((size_t)b * C_ + c) * T_ + t) * N_ + n0 + q * 4);
        xs[c][q * 4 + 0] = v.x; xs[c][q * 4 + 1] = v.y;
        xs[c][q * 4 + 2] = v.z; xs[c][q * 4 + 3] = v.w;
    }
    __syncthreads();

    {
        int n = tid & 127;
        int p = tid >> 7;
        float a0 = 0.f, a1 = 0.f, a2 = 0.f, a3 = 0.f;
        #pragma unroll 16
        for (int c = 0; c < 64; c++) {
            float xv = xs[c][n];
            a0 = fmaf(xv, su[p * 4 + 0][c], a0);
            a1 = fmaf(xv, su[p * 4 + 1][c], a1);
            a2 = fmaf(xv, su[p * 4 + 2][c], a2);
            a3 = fmaf(xv, su[p * 4 + 3][c], a3);
        }
        float* dstp = (p == 0 ? g_asrc : g_adst) + ((size_t)g * N_ + n0 + n) * H_;
        dstp[0] = a0; dstp[1] = a1; dstp[2] = a2; dstp[3] = a3;
    }

    #pragma unroll
    for (int i = tid; i < 128 * 16; i += 256) {
        int n = i >> 4, q = i & 15;
        float4 v = {xs[q * 4 + 0][n], xs[q * 4 + 1][n], xs[q * 4 + 2][n], xs[q * 4 + 3][n]};
        *(float4*)(g_xt + ((size_t)g * N_ + n0 + n) * C_ + q * 4) = v;
    }
}

// ============================================================
// K2: aggregate in x-space, warp per (g,dst). fp32 z epilogue.
// ============================================================
__global__ void __launch_bounds__(256) aggregate_kernel() {
    __shared__ float4 s_as[N_];
    __shared__ ull    s_wp[8][32][4];
    __shared__ int    s_src[8][32];
    int g    = blockIdx.y;
    int tid  = threadIdx.x;
    int warp = tid >> 5, lane = tid & 31;

    const float4* asrc_g = (const float4*)(g_asrc + (size_t)g * N_ * H_);
    for (int i = tid; i < N_; i += 256) s_as[i] = asrc_g[i];
    __syncthreads();

    int dst   = (blockIdx.x << 3) + warp;
    int start = g_rowptr[dst];
    int end   = g_rowptr[dst + 1];

    float4 ad = *(const float4*)(g_adst + ((size_t)g * N_ + dst) * H_);
    float4 sa = s_as[dst];
    float ws0 = __expf(lrelu(sa.x + ad.x));
    float ws1 = __expf(lrelu(sa.y + ad.y));
    float ws2 = __expf(lrelu(sa.z + ad.z));
    float ws3 = __expf(lrelu(sa.w + ad.w));

    const ull* xgu = (const ull*)(g_xt + (size_t)g * N_ * C_);

    ull xdv = xgu[(size_t)dst * 32 + lane];
    ull acc0 = fma2(pack2(ws0, ws0), xdv, 0ULL);
    ull acc1 = fma2(pack2(ws1, ws1), xdv, 0ULL);
    ull acc2 = fma2(pack2(ws2, ws2), xdv, 0ULL);
    ull acc3 = fma2(pack2(ws3, ws3), xdv, 0ULL);

    float p0 = 0.f, p1 = 0.f, p2 = 0.f, p3 = 0.f;

    for (int base = start; base < end; base += 32) {
        int e = base + lane;
        int src = 0;
        float w0 = 0.f, w1 = 0.f, w2 = 0.f, w3 = 0.f;
        if (e < end) {
            src = g_col[e];
            float4 a = s_as[src];
            w0 = __expf(lrelu(a.x + ad.x));
            w1 = __expf(lrelu(a.y + ad.y));
            w2 = __expf(lrelu(a.z + ad.z));
            w3 = __expf(lrelu(a.w + ad.w));
        }
        p0 += w0; p1 += w1; p2 += w2; p3 += w3;
        ulonglong2 pA, pB;
        pA.x = pack2(w0, w0); pA.y = pack2(w1, w1);
        pB.x = pack2(w2, w2); pB.y = pack2(w3, w3);
        *(ulonglong2*)&s_wp[warp][lane][0] = pA;
        *(ulonglong2*)&s_wp[warp][lane][2] = pB;
        s_src[warp][lane] = src;
        __syncwarp();

        int cnt = min(32, end - base);
        int sj = s_src[warp][0];
        ull xv = xgu[(size_t)sj * 32 + lane];
        for (int j = 0; j < cnt; j++) {
            int jn = min(j + 1, cnt - 1);
            int sn = s_src[warp][jn];
            ull xn = xgu[(size_t)sn * 32 + lane];
            ulonglong2 wA = *(const ulonglong2*)&s_wp[warp][j][0];
            ulonglong2 wB = *(const ulonglong2*)&s_wp[warp][j][2];
            acc0 = fma2(wA.x, xv, acc0);
            acc1 = fma2(wA.y, xv, acc1);
            acc2 = fma2(wB.x, xv, acc2);
            acc3 = fma2(wB.y, xv, acc3);
            xv = xn;
        }
        __syncwarp();
    }

    #pragma unroll
    for (int o = 16; o > 0; o >>= 1) {
        p0 += __shfl_xor_sync(0xffffffffu, p0, o);
        p1 += __shfl_xor_sync(0xffffffffu, p1, o);
        p2 += __shfl_xor_sync(0xffffffffu, p2, o);
        p3 += __shfl_xor_sync(0xffffffffu, p3, o);
    }
    float i0 = 1.0f / (p0 + ws0);
    float i1 = 1.0f / (p1 + ws1);
    float i2 = 1.0f / (p2 + ws2);
    float i3 = 1.0f / (p3 + ws3);

    float lo, hi;
    float* zp = g_z + ((size_t)g * N_ + dst) * HC_ + 2 * lane;
    unpack2(acc0, lo, hi); *(float2*)(zp +   0) = make_float2(lo * i0, hi * i0);
    unpack2(acc1, lo, hi); *(float2*)(zp +  64) = make_float2(lo * i1, hi * i1);
    unpack2(acc2, lo, hi); *(float2*)(zp + 128) = make_float2(lo * i2, hi * i2);
    unpack2(acc3, lo, hi); *(float2*)(zp + 192) = make_float2(lo * i3, hi * i3);
}

// ============================================================
// K3: out = z @ Wt + bias -> [B,Co,T,N], tensor cores.
// z fp32 in smem, A-frags split to tf32 hi/lo in registers;
// W presplit in gmem. CTA 256 thr, tile 128n x 64co; warp 16n x 64co.
// K chunks of 16. grid (4, 96) = 384 blocks.
// ============================================================
#define KCH 16
__global__ void __launch_bounds__(256) gemm2_tc_kernel(const float* __restrict__ bias,
                                                       float* __restrict__ out) {
    __shared__ float    s_z [128][20];   // [n][k] pitch 20: conflict-free A frags
    __shared__ unsigned s_wh[KCH][72];   // [k][co] pitch 72: conflict-free B frags
    __shared__ unsigned s_wl[KCH][72];

    int g   = blockIdx.y;
    int qt  = blockIdx.x;          // n-quarter
    int b   = g / T_;
    int t   = g - b * T_;
    int tid = threadIdx.x;
    int w    = tid >> 5;
    int lane = tid & 31;
    int gid  = lane >> 2;   // 0..7
    int tig  = lane & 3;    // 0..3

    float acc[8][4];
    #pragma unroll
    for (int ct = 0; ct < 8; ct++)
        #pragma unroll
        for (int j = 0; j < 4; j++) acc[ct][j] = 0.0f;

    const float* zbase = g_z + ((size_t)g * N_ + qt * 128) * HC_;

    for (int kk = 0; kk < HC_ / KCH; kk++) {
        __syncthreads();
        // stage z chunk [128 n][16 k] fp32  (512 float4)
        #pragma unroll
        for (int i = tid; i < 512; i += 256) {
            int n = i >> 2, q4 = i & 3;
            *(float4*)&s_z[n][q4 * 4] = *(const float4*)(zbase + (size_t)n * HC_ + kk * KCH + q4 * 4);
        }
        // stage w chunk [16 k][64 co] hi+lo (1 uint4 each per thread)
        {
            int k = tid >> 4, q4 = tid & 15;
            *(uint4*)&s_wh[k][q4 * 4] = *(const uint4*)(g_Wth + (size_t)(kk * KCH + k) * CO_ + q4 * 4);
            *(uint4*)&s_wl[k][q4 * 4] = *(const uint4*)(g_Wtl + (size_t)(kk * KCH + k) * CO_ + q4 * 4);
        }
        __syncthreads();

        #pragma unroll
        for (int q = 0; q < 2; q++) {
            int k0 = q * 8;
            int rb = w * 16 + gid;
            unsigned ah0, ah1, ah2, ah3, al0, al1, al2, al3;
            tf32_split(s_z[rb    ][k0 + tig    ], ah0, al0);
            tf32_split(s_z[rb + 8][k0 + tig    ], ah1, al1);
            tf32_split(s_z[rb    ][k0 + tig + 4], ah2, al2);
            tf32_split(s_z[rb + 8][k0 + tig + 4], ah3, al3);
            #pragma unroll
            for (int ct = 0; ct < 8; ct++) {
                int co = ct * 8 + gid;
                unsigned bh0 = s_wh[k0 + tig    ][co];
                unsigned bh1 = s_wh[k0 + tig + 4][co];
                unsigned bl0 = s_wl[k0 + tig    ][co];
                unsigned bl1 = s_wl[k0 + tig + 4][co];
                mma_tf32(acc[ct][0], acc[ct][1], acc[ct][2], acc[ct][3],
                         ah0, ah1, ah2, ah3, bh0, bh1);
                mma_tf32(acc[ct][0], acc[ct][1], acc[ct][2], acc[ct][3],
                         al0, al1, al2, al3, bh0, bh1);
                mma_tf32(acc[ct][0], acc[ct][1], acc[ct][2], acc[ct][3],
                         ah0, ah1, ah2, ah3, bl0, bl1);
            }
        }
    }

    // epilogue: direct STG with bias
    int n_g = qt * 128 + w * 16 + gid;
    #pragma unroll
    for (int ct = 0; ct < 8; ct++) {
        int co = ct * 8 + 2 * tig;
        float bv0 = __ldg(&bias[co]);
        float bv1 = __ldg(&bias[co + 1]);
        float* o0 = out + (((size_t)b * CO_ + co)     * T_ + t) * N_ + n_g;
        float* o1 = out + (((size_t)b * CO_ + co + 1) * T_ + t) * N_ + n_g;
        o0[0] = acc[ct][0] + bv0;
        o1[0] = acc[ct][1] + bv1;
        o0[8] = acc[ct][2] + bv0;
        o1[8] = acc[ct][3] + bv1;
    }
}

// ============================================================
extern "C" void kernel_launch(void* const* d_in, const int* in_sizes, int n_in,
                              void* d_out, int out_size) {
    const float* x        = (const float*)d_in[0];
    const int*   ei       = (const int*)  d_in[1];
    const float* W        = (const float*)d_in[2];
    const float* att_src  = (const float*)d_in[3];
    const float* att_dst  = (const float*)d_in[4];
    const float* bias     = (const float*)d_in[5];
    float*       out      = (float*)d_out;
    int E = in_sizes[1] / 2;

    setup_kernel<<<2, 512>>>(ei, E, W, att_src, att_dst);
    xt_asrc_kernel<<<dim3(N_ / 128, G_), 256>>>(x);
    aggregate_kernel<<<dim3(N_ / 8, G_), 256>>>();
    gemm2_tc_kernel<<<dim3(N_ / 128, G_), 256>>>(bias, out);
}

// round 13
// speedup vs baseline: 1.6688x; 1.0334x over previous
#include <cuda_runtime.h>
#include <cstdint>

#define B_  8
#define C_  64
#define T_  12
#define N_  512
#define G_  (B_ * T_)      // 96
#define H_  4
#define CO_ 64
#define HC_ (H_ * CO_)     // 256
#define NEG_SLOPE 0.2f
#define EMAX 16384

typedef unsigned long long ull;

// ---------------- device scratch ----------------
__device__ float    g_xt[(size_t)G_ * N_ * C_];    // [G,N,64]
__device__ float    g_z [(size_t)G_ * N_ * HC_];   // [G,N,256] fp32
__device__ float    g_asrc[(size_t)G_ * N_ * H_];  // [G,N,4]
__device__ float    g_adst[(size_t)G_ * N_ * H_];
__device__ float    g_u[2 * H_ * C_];              // [src/dst][h][c]
__device__ uint4    g_Wp[8192];                    // [kk][q][tig][co] packed (wh,wh+4,wl,wl+4)
__device__ int      g_rowptr[N_ + 1];
__device__ int      g_col[EMAX];

__device__ __forceinline__ float lrelu(float x) {
    return x > 0.0f ? x : NEG_SLOPE * x;
}
__device__ __forceinline__ ull pack2(float lo, float hi) {
    ull d;
    asm("mov.b64 %0, {%1, %2};" : "=l"(d) : "r"(__float_as_uint(lo)), "r"(__float_as_uint(hi)));
    return d;
}
__device__ __forceinline__ void unpack2(ull v, float& lo, float& hi) {
    unsigned a, b;
    asm("mov.b64 {%0, %1}, %2;" : "=r"(a), "=r"(b) : "l"(v));
    lo = __uint_as_float(a); hi = __uint_as_float(b);
}
__device__ __forceinline__ ull fma2(ull a, ull b, ull c) {
    ull d;
    asm("fma.rn.f32x2 %0, %1, %2, %3;" : "=l"(d) : "l"(a), "l"(b), "l"(c));
    return d;
}
__device__ __forceinline__ void tf32_split(float v, unsigned& hi, unsigned& lo) {
    asm("cvt.rna.tf32.f32 %0, %1;" : "=r"(hi) : "f"(v));
    float r = v - __uint_as_float(hi);
    asm("cvt.rna.tf32.f32 %0, %1;" : "=r"(lo) : "f"(r));
}
__device__ __forceinline__ void mma_tf32(float& d0, float& d1, float& d2, float& d3,
                                         unsigned a0, unsigned a1, unsigned a2, unsigned a3,
                                         unsigned b0, unsigned b1) {
    asm volatile("mma.sync.aligned.m16n8k8.row.col.f32.tf32.tf32.f32 "
                 "{%0,%1,%2,%3}, {%4,%5,%6,%7}, {%8,%9}, {%0,%1,%2,%3};"
                 : "+f"(d0), "+f"(d1), "+f"(d2), "+f"(d3)
                 : "r"(a0), "r"(a1), "r"(a2), "r"(a3), "r"(b0), "r"(b1));
}

// ============================================================
// K0: setup. block 0: CSR build. block 1: prep u + packed W. 512 thr.
// ============================================================
__global__ void setup_kernel(const int* __restrict__ ei, int E,
                             const float* __restrict__ W,
                             const float* __restrict__ att_src,
                             const float* __restrict__ att_dst) {
    int tid = threadIdx.x;
    if (blockIdx.x == 0) {
        __shared__ int cnt[N_];
        __shared__ int cur[N_];
        __shared__ int wsum[16];
        cnt[tid] = 0;
        __syncthreads();
        const int* dst = ei + E;
        for (int e = tid; e < E; e += N_) atomicAdd(&cnt[dst[e]], 1);
        __syncthreads();

        int v = cnt[tid];
        int lane = tid & 31, wid = tid >> 5;
        int inc = v;
        #pragma unroll
        for (int o = 1; o < 32; o <<= 1) {
            int u = __shfl_up_sync(0xffffffffu, inc, o);
            if (lane >= o) inc += u;
        }
        if (lane == 31) wsum[wid] = inc;
        __syncthreads();
        if (wid == 0 && lane < 16) {
            int ws = wsum[lane];
            int wi = ws;
            #pragma unroll
            for (int o = 1; o < 16; o <<= 1) {
                int u = __shfl_up_sync(0x0000ffffu, wi, o);
                if (lane >= o) wi += u;
            }
            wsum[lane] = wi - ws;
        }
        __syncthreads();
        int excl = inc - v + wsum[wid];
        g_rowptr[tid] = excl;
        cur[tid] = excl;
        if (tid == N_ - 1) g_rowptr[N_] = excl + v;
        __syncthreads();

        for (int e = tid; e < E; e += N_) {
            int d = dst[e];
            int p = atomicAdd(&cur[d], 1);
            g_col[p] = ei[e];
        }
    } else {
        __shared__ float satt[2 * H_ * CO_];
        satt[tid] = (tid < 256) ? att_src[tid] : att_dst[tid - 256];
        __syncthreads();

        {
            int k = tid;                 // 512 = 2*4*64
            int p = k >> 8;
            int h = (k >> 6) & 3;
            int c = k & 63;
            const float* wrow = W + (size_t)c * HC_ + h * CO_;
            const float* av = satt + p * 256 + h * CO_;
            float s = 0.0f;
            #pragma unroll 16
            for (int co = 0; co < CO_; co++) s += wrow[co] * av[co];
            g_u[k] = s;
        }
        // packed W: g_Wp[((kk*4+q)*4+tig)*64+co] = (wh[k],wh[k+4],wl[k],wl[k+4]),
        // k = kk*32 + q*8 + tig, wt = 0.25*W[c][h*64+co] with k = h*64+c
        for (int idx = tid; idx < 8192; idx += 512) {
            int co  = idx & 63;
            int tig = (idx >> 6) & 3;
            int q   = (idx >> 8) & 3;
            int kk  = idx >> 10;
            int k   = kk * 32 + q * 8 + tig;
            int h  = k >> 6,  c  = k & 63;
            int k2 = k + 4;
            int h2 = k2 >> 6, c2 = k2 & 63;
            float w0 = 0.25f * W[(size_t)c  * HC_ + h  * CO_ + co];
            float w1 = 0.25f * W[(size_t)c2 * HC_ + h2 * CO_ + co];
            uint4 pv;
            tf32_split(w0, pv.x, pv.z);
            tf32_split(w1, pv.y, pv.w);
            g_Wp[idx] = pv;
        }
    }
}

// ============================================================
// K1: per g: transpose x -> xt, asrc/adst = x . u
// grid (4, 96), block 256.
// ============================================================
__global__ void xt_asrc_kernel(const float* __restrict__ x) {
    __shared__ float xs[64][129];
    __shared__ float su[8][64];
    int g  = blockIdx.y;
    int n0 = blockIdx.x * 128;
    int b  = g / T_;
    int t  = g - b * T_;
    int tid = threadIdx.x;

    for (int i = tid; i < 512; i += 256) su[i >> 6][i & 63] = g_u[i];
    #pragma unroll
    for (int i = tid; i < 64 * 32; i += 256) {
        int c = i >> 5, q = i & 31;
        float4 v = *(const float4*)(x + (((size_t)b * C_ + c) * T_ + t) * N_ + n0 + q * 4);
        xs[c][q * 4 + 0] = v.x; xs[c][q * 4 + 1] = v.y;
        xs[c][q * 4 + 2] = v.z; xs[c][q * 4 + 3] = v.w;
    }
    __syncthreads();

    {
        int n = tid & 127;
        int p = tid >> 7;
        float a0 = 0.f, a1 = 0.f, a2 = 0.f, a3 = 0.f;
        #pragma unroll 16
        for (int c = 0; c < 64; c++) {
            float xv = xs[c][n];
            a0 = fmaf(xv, su[p * 4 + 0][c], a0);
            a1 = fmaf(xv, su[p * 4 + 1][c], a1);
            a2 = fmaf(xv, su[p * 4 + 2][c], a2);
            a3 = fmaf(xv, su[p * 4 + 3][c], a3);
        }
        float* dstp = (p == 0 ? g_asrc : g_adst) + ((size_t)g * N_ + n0 + n) * H_;
        dstp[0] = a0; dstp[1] = a1; dstp[2] = a2; dstp[3] = a3;
    }

    #pragma unroll
    for (int i = tid; i < 128 * 16; i += 256) {
        int n = i >> 4, q = i & 15;
        float4 v = {xs[q * 4 + 0][n], xs[q * 4 + 1][n], xs[q * 4 + 2][n], xs[q * 4 + 3][n]};
        *(float4*)(g_xt + ((size_t)g * N_ + n0 + n) * C_ + q * 4) = v;
    }
}

// ============================================================
// K2: aggregate in x-space, warp per (g,dst). (unchanged, proven)
// ============================================================
__global__ void __launch_bounds__(256) aggregate_kernel() {
    __shared__ float4 s_as[N_];
    __shared__ ull    s_wp[8][32][4];
    __shared__ int    s_src[8][32];
    int g    = blockIdx.y;
    int tid  = threadIdx.x;
    int warp = tid >> 5, lane = tid & 31;

    const float4* asrc_g = (const float4*)(g_asrc + (size_t)g * N_ * H_);
    for (int i = tid; i < N_; i += 256) s_as[i] = asrc_g[i];
    __syncthreads();

    int dst   = (blockIdx.x << 3) + warp;
    int start = g_rowptr[dst];
    int end   = g_rowptr[dst + 1];

    float4 ad = *(const float4*)(g_adst + ((size_t)g * N_ + dst) * H_);
    float4 sa = s_as[dst];
    float ws0 = __expf(lrelu(sa.x + ad.x));
    float ws1 = __expf(lrelu(sa.y + ad.y));
    float ws2 = __expf(lrelu(sa.z + ad.z));
    float ws3 = __expf(lrelu(sa.w + ad.w));

    const ull* xgu = (const ull*)(g_xt + (size_t)g * N_ * C_);

    ull xdv = xgu[(size_t)dst * 32 + lane];
    ull acc0 = fma2(pack2(ws0, ws0), xdv, 0ULL);
    ull acc1 = fma2(pack2(ws1, ws1), xdv, 0ULL);
    ull acc2 = fma2(pack2(ws2, ws2), xdv, 0ULL);
    ull acc3 = fma2(pack2(ws3, ws3), xdv, 0ULL);

    float p0 = 0.f, p1 = 0.f, p2 = 0.f, p3 = 0.f;

    for (int base = start; base < end; base += 32) {
        int e = base + lane;
        int src = 0;
        float w0 = 0.f, w1 = 0.f, w2 = 0.f, w3 = 0.f;
        if (e < end) {
            src = g_col[e];
            float4 a = s_as[src];
            w0 = __expf(lrelu(a.x + ad.x));
            w1 = __expf(lrelu(a.y + ad.y));
            w2 = __expf(lrelu(a.z + ad.z));
            w3 = __expf(lrelu(a.w + ad.w));
        }
        p0 += w0; p1 += w1; p2 += w2; p3 += w3;
        ulonglong2 pA, pB;
        pA.x = pack2(w0, w0); pA.y = pack2(w1, w1);
        pB.x = pack2(w2, w2); pB.y = pack2(w3, w3);
        *(ulonglong2*)&s_wp[warp][lane][0] = pA;
        *(ulonglong2*)&s_wp[warp][lane][2] = pB;
        s_src[warp][lane] = src;
        __syncwarp();

        int cnt = min(32, end - base);
        int sj = s_src[warp][0];
        ull xv = xgu[(size_t)sj * 32 + lane];
        for (int j = 0; j < cnt; j++) {
            int jn = min(j + 1, cnt - 1);
            int sn = s_src[warp][jn];
            ull xn = xgu[(size_t)sn * 32 + lane];
            ulonglong2 wA = *(const ulonglong2*)&s_wp[warp][j][0];
            ulonglong2 wB = *(const ulonglong2*)&s_wp[warp][j][2];
            acc0 = fma2(wA.x, xv, acc0);
            acc1 = fma2(wA.y, xv, acc1);
            acc2 = fma2(wB.x, xv, acc2);
            acc3 = fma2(wB.y, xv, acc3);
            xv = xn;
        }
        __syncwarp();
    }

    #pragma unroll
    for (int o = 16; o > 0; o >>= 1) {
        p0 += __shfl_xor_sync(0xffffffffu, p0, o);
        p1 += __shfl_xor_sync(0xffffffffu, p1, o);
        p2 += __shfl_xor_sync(0xffffffffu, p2, o);
        p3 += __shfl_xor_sync(0xffffffffu, p3, o);
    }
    float i0 = 1.0f / (p0 + ws0);
    float i1 = 1.0f / (p1 + ws1);
    float i2 = 1.0f / (p2 + ws2);
    float i3 = 1.0f / (p3 + ws3);

    float lo, hi;
    float* zp = g_z + ((size_t)g * N_ + dst) * HC_ + 2 * lane;
    unpack2(acc0, lo, hi); *(float2*)(zp +   0) = make_float2(lo * i0, hi * i0);
    unpack2(acc1, lo, hi); *(float2*)(zp +  64) = make_float2(lo * i1, hi * i1);
    unpack2(acc2, lo, hi); *(float2*)(zp + 128) = make_float2(lo * i2, hi * i2);
    unpack2(acc3, lo, hi); *(float2*)(zp + 192) = make_float2(lo * i3, hi * i3);
}

// ============================================================
// K3: out = z @ Wt + bias -> [B,Co,T,N], tensor cores.
// z fp32 in smem (A split in regs); W packed uint4 frags in smem.
// CTA 256 thr, tile 128n x 64co; warp 16n x 64co. KCH=32 (8 chunks).
// grid (4, 96) = 384 blocks.
// ============================================================
#define KCH 32
__global__ void __launch_bounds__(256) gemm2_tc_kernel(const float* __restrict__ bias,
                                                       float* __restrict__ out) {
    __shared__ float s_z[128][36];        // [n][k] pitch 36: A LDS.32 bank = lane
    __shared__ uint4 s_w[4][4][66];       // [q][tig][co] pitch 66: LDS.128 conflict-free

    int g   = blockIdx.y;
    int qt  = blockIdx.x;          // n-quarter
    int b   = g / T_;
    int t   = g - b * T_;
    int tid = threadIdx.x;
    int w    = tid >> 5;
    int lane = tid & 31;
    int gid  = lane >> 2;   // 0..7
    int tig  = lane & 3;    // 0..3

    float acc[8][4];
    #pragma unroll
    for (int ct = 0; ct < 8; ct++)
        #pragma unroll
        for (int j = 0; j < 4; j++) acc[ct][j] = 0.0f;

    const float* zbase = g_z + ((size_t)g * N_ + qt * 128) * HC_;

    for (int kk = 0; kk < HC_ / KCH; kk++) {
        __syncthreads();
        // stage z chunk [128 n][32 k] fp32 (1024 float4)
        #pragma unroll
        for (int i = tid; i < 1024; i += 256) {
            int n = i >> 3, q4 = i & 7;
            *(float4*)&s_z[n][q4 * 4] = *(const float4*)(zbase + (size_t)n * HC_ + kk * KCH + q4 * 4);
        }
        // stage packed w frags (1024 uint4)
        #pragma unroll
        for (int i = tid; i < 1024; i += 256) {
            int co = i & 63, tg = (i >> 6) & 3, q = i >> 8;
            s_w[q][tg][co] = g_Wp[kk * 1024 + i];
        }
        __syncthreads();

        #pragma unroll
        for (int q = 0; q < 4; q++) {
            int k0 = q * 8;
            int rb = w * 16 + gid;
            unsigned ah0, ah1, ah2, ah3, al0, al1, al2, al3;
            tf32_split(s_z[rb    ][k0 + tig    ], ah0, al0);
            tf32_split(s_z[rb + 8][k0 + tig    ], ah1, al1);
            tf32_split(s_z[rb    ][k0 + tig + 4], ah2, al2);
            tf32_split(s_z[rb + 8][k0 + tig + 4], ah3, al3);
            #pragma unroll
            for (int ct = 0; ct < 8; ct++) {
                uint4 wv = s_w[q][tig][ct * 8 + gid];   // (bh0, bh1, bl0, bl1)
                mma_tf32(acc[ct][0], acc[ct][1], acc[ct][2], acc[ct][3],
                         ah0, ah1, ah2, ah3, wv.x, wv.y);
                mma_tf32(acc[ct][0], acc[ct][1], acc[ct][2], acc[ct][3],
                         al0, al1, al2, al3, wv.x, wv.y);
                mma_tf32(acc[ct][0], acc[ct][1], acc[ct][2], acc[ct][3],
                         ah0, ah1, ah2, ah3, wv.z, wv.w);
            }
        }
    }

    // epilogue: direct STG with bias
    int n_g = qt * 128 + w * 16 + gid;
    #pragma unroll
    for (int ct = 0; ct < 8; ct++) {
        int co = ct * 8 + 2 * tig;
        float bv0 = __ldg(&bias[co]);
        float bv1 = __ldg(&bias[co + 1]);
        float* o0 = out + (((size_t)b * CO_ + co)     * T_ + t) * N_ + n_g;
        float* o1 = out + (((size_t)b * CO_ + co + 1) * T_ + t) * N_ + n_g;
        o0[0] = acc[ct][0] + bv0;
        o1[0] = acc[ct][1] + bv1;
        o0[8] = acc[ct][2] + bv0;
        o1[8] = acc[ct][3] + bv1;
    }
}

// ============================================================
extern "C" void kernel_launch(void* const* d_in, const int* in_sizes, int n_in,
                              void* d_out, int out_size) {
    const float* x        = (const float*)d_in[0];
    const int*   ei       = (const int*)  d_in[1];
    const float* W        = (const float*)d_in[2];
    const float* att_src  = (const float*)d_in[3];
    const float* att_dst  = (const float*)d_in[4];
    const float* bias     = (const float*)d_in[5];
    float*       out      = (float*)d_out;
    int E = in_sizes[1] / 2;

    setup_kernel<<<2, 512>>>(ei, E, W, att_src, att_dst);
    xt_asrc_kernel<<<dim3(N_ / 128, G_), 256>>>(x);
    aggregate_kernel<<<dim3(N_ / 8, G_), 256>>>();
    gemm2_tc_kernel<<<dim3(N_ / 128, G_), 256>>>(bias, out);
}

// round 14
// speedup vs baseline: 1.6888x; 1.0120x over previous
#include <cuda_runtime.h>
#include <cstdint>

#define B_  8
#define C_  64
#define T_  12
#define N_  512
#define G_  (B_ * T_)      // 96
#define H_  4
#define CO_ 64
#define HC_ (H_ * CO_)     // 256
#define NEG_SLOPE 0.2f
#define EMAX 16384

typedef unsigned long long ull;

// ---------------- device scratch ----------------
__device__ float    g_xt[(size_t)G_ * N_ * C_];    // [G,N,64]
__device__ float    g_z [(size_t)G_ * N_ * HC_];   // [G,N,256] fp32
__device__ float    g_asrc[(size_t)G_ * N_ * H_];  // [G,N,4]
__device__ float    g_adst[(size_t)G_ * N_ * H_];
__device__ float    g_u[2 * H_ * C_];              // [src/dst][h][c]
__device__ uint4    g_Wp[8192];                    // [kk][q][tig][co] packed (wh,wh+4,wl,wl+4)
__device__ int      g_rowptr[N_ + 1];
__device__ int      g_col[EMAX];

__device__ __forceinline__ float lrelu(float x) {
    return x > 0.0f ? x : NEG_SLOPE * x;
}
__device__ __forceinline__ ull pack2(float lo, float hi) {
    ull d;
    asm("mov.b64 %0, {%1, %2};" : "=l"(d) : "r"(__float_as_uint(lo)), "r"(__float_as_uint(hi)));
    return d;
}
__device__ __forceinline__ void unpack2(ull v, float& lo, float& hi) {
    unsigned a, b;
    asm("mov.b64 {%0, %1}, %2;" : "=r"(a), "=r"(b) : "l"(v));
    lo = __uint_as_float(a); hi = __uint_as_float(b);
}
__device__ __forceinline__ ull fma2(ull a, ull b, ull c) {
    ull d;
    asm("fma.rn.f32x2 %0, %1, %2, %3;" : "=l"(d) : "l"(a), "l"(b), "l"(c));
    return d;
}
__device__ __forceinline__ void tf32_split(float v, unsigned& hi, unsigned& lo) {
    asm("cvt.rna.tf32.f32 %0, %1;" : "=r"(hi) : "f"(v));
    float r = v - __uint_as_float(hi);
    asm("cvt.rna.tf32.f32 %0, %1;" : "=r"(lo) : "f"(r));
}
__device__ __forceinline__ void mma_tf32(float& d0, float& d1, float& d2, float& d3,
                                         unsigned a0, unsigned a1, unsigned a2, unsigned a3,
                                         unsigned b0, unsigned b1) {
    asm volatile("mma.sync.aligned.m16n8k8.row.col.f32.tf32.tf32.f32 "
                 "{%0,%1,%2,%3}, {%4,%5,%6,%7}, {%8,%9}, {%0,%1,%2,%3};"
                 : "+f"(d0), "+f"(d1), "+f"(d2), "+f"(d3)
                 : "r"(a0), "r"(a1), "r"(a2), "r"(a3), "r"(b0), "r"(b1));
}

// ============================================================
// K0: setup. block 0: CSR build. block 1: prep u + packed W. 512 thr.
// ============================================================
__global__ void setup_kernel(const int* __restrict__ ei, int E,
                             const float* __restrict__ W,
                             const float* __restrict__ att_src,
                             const float* __restrict__ att_dst) {
    int tid = threadIdx.x;
    if (blockIdx.x == 0) {
        __shared__ int cnt[N_];
        __shared__ int cur[N_];
        __shared__ int wsum[16];
        cnt[tid] = 0;
        __syncthreads();
        const int* dst = ei + E;
        for (int e = tid; e < E; e += N_) atomicAdd(&cnt[dst[e]], 1);
        __syncthreads();

        int v = cnt[tid];
        int lane = tid & 31, wid = tid >> 5;
        int inc = v;
        #pragma unroll
        for (int o = 1; o < 32; o <<= 1) {
            int u = __shfl_up_sync(0xffffffffu, inc, o);
            if (lane >= o) inc += u;
        }
        if (lane == 31) wsum[wid] = inc;
        __syncthreads();
        if (wid == 0 && lane < 16) {
            int ws = wsum[lane];
            int wi = ws;
            #pragma unroll
            for (int o = 1; o < 16; o <<= 1) {
                int u = __shfl_up_sync(0x0000ffffu, wi, o);
                if (lane >= o) wi += u;
            }
            wsum[lane] = wi - ws;
        }
        __syncthreads();
        int excl = inc - v + wsum[wid];
        g_rowptr[tid] = excl;
        cur[tid] = excl;
        if (tid == N_ - 1) g_rowptr[N_] = excl + v;
        __syncthreads();

        for (int e = tid; e < E; e += N_) {
            int d = dst[e];
            int p = atomicAdd(&cur[d], 1);
            g_col[p] = ei[e];
        }
    } else {
        __shared__ float satt[2 * H_ * CO_];
        satt[tid] = (tid < 256) ? att_src[tid] : att_dst[tid - 256];
        __syncthreads();

        {
            int k = tid;                 // 512 = 2*4*64
            int p = k >> 8;
            int h = (k >> 6) & 3;
            int c = k & 63;
            const float* wrow = W + (size_t)c * HC_ + h * CO_;
            const float* av = satt + p * 256 + h * CO_;
            float s = 0.0f;
            #pragma unroll 16
            for (int co = 0; co < CO_; co++) s += wrow[co] * av[co];
            g_u[k] = s;
        }
        // packed W: g_Wp[((kk*4+q)*4+tig)*64+co] = (wh[k],wh[k+4],wl[k],wl[k+4]),
        // k = kk*32 + q*8 + tig, wt = 0.25*W[c][h*64+co] with k = h*64+c
        for (int idx = tid; idx < 8192; idx += 512) {
            int co  = idx & 63;
            int tig = (idx >> 6) & 3;
            int q   = (idx >> 8) & 3;
            int kk  = idx >> 10;
            int k   = kk * 32 + q * 8 + tig;
            int h  = k >> 6,  c  = k & 63;
            int k2 = k + 4;
            int h2 = k2 >> 6, c2 = k2 & 63;
            float w0 = 0.25f * W[(size_t)c  * HC_ + h  * CO_ + co];
            float w1 = 0.25f * W[(size_t)c2 * HC_ + h2 * CO_ + co];
            uint4 pv;
            tf32_split(w0, pv.x, pv.z);
            tf32_split(w1, pv.y, pv.w);
            g_Wp[idx] = pv;
        }
    }
}

// ============================================================
// K1: per g: transpose x -> xt, asrc/adst = x . u
// grid (4, 96), block 256.
// ============================================================
__global__ void xt_asrc_kernel(const float* __restrict__ x) {
    __shared__ float xs[64][129];
    __shared__ float su[8][64];
    int g  = blockIdx.y;
    int n0 = blockIdx.x * 128;
    int b  = g / T_;
    int t  = g - b * T_;
    int tid = threadIdx.x;

    for (int i = tid; i < 512; i += 256) su[i >> 6][i & 63] = g_u[i];
    #pragma unroll
    for (int i = tid; i < 64 * 32; i += 256) {
        int c = i >> 5, q = i & 31;
        float4 v = *(const float4*)(x + (((size_t)b * C_ + c) * T_ + t) * N_ + n0 + q * 4);
        xs[c][q * 4 + 0] = v.x; xs[c][q * 4 + 1] = v.y;
        xs[c][q * 4 + 2] = v.z; xs[c][q * 4 + 3] = v.w;
    }
    __syncthreads();

    {
        int n = tid & 127;
        int p = tid >> 7;
        float a0 = 0.f, a1 = 0.f, a2 = 0.f, a3 = 0.f;
        #pragma unroll 16
        for (int c = 0; c < 64; c++) {
            float xv = xs[c][n];
            a0 = fmaf(xv, su[p * 4 + 0][c], a0);
            a1 = fmaf(xv, su[p * 4 + 1][c], a1);
            a2 = fmaf(xv, su[p * 4 + 2][c], a2);
            a3 = fmaf(xv, su[p * 4 + 3][c], a3);
        }
        float* dstp = (p == 0 ? g_asrc : g_adst) + ((size_t)g * N_ + n0 + n) * H_;
        dstp[0] = a0; dstp[1] = a1; dstp[2] = a2; dstp[3] = a3;
    }

    #pragma unroll
    for (int i = tid; i < 128 * 16; i += 256) {
        int n = i >> 4, q = i & 15;
        float4 v = {xs[q * 4 + 0][n], xs[q * 4 + 1][n], xs[q * 4 + 2][n], xs[q * 4 + 3][n]};
        *(float4*)(g_xt + ((size_t)g * N_ + n0 + n) * C_ + q * 4) = v;
    }
}

// ============================================================
// K2: aggregate in x-space, warp per (g,dst). (unchanged, proven)
// ============================================================
__global__ void __launch_bounds__(256) aggregate_kernel() {
    __shared__ float4 s_as[N_];
    __shared__ ull    s_wp[8][32][4];
    __shared__ int    s_src[8][32];
    int g    = blockIdx.y;
    int tid  = threadIdx.x;
    int warp = tid >> 5, lane = tid & 31;

    const float4* asrc_g = (const float4*)(g_asrc + (size_t)g * N_ * H_);
    for (int i = tid; i < N_; i += 256) s_as[i] = asrc_g[i];
    __syncthreads();

    int dst   = (blockIdx.x << 3) + warp;
    int start = g_rowptr[dst];
    int end   = g_rowptr[dst + 1];

    float4 ad = *(const float4*)(g_adst + ((size_t)g * N_ + dst) * H_);
    float4 sa = s_as[dst];
    float ws0 = __expf(lrelu(sa.x + ad.x));
    float ws1 = __expf(lrelu(sa.y + ad.y));
    float ws2 = __expf(lrelu(sa.z + ad.z));
    float ws3 = __expf(lrelu(sa.w + ad.w));

    const ull* xgu = (const ull*)(g_xt + (size_t)g * N_ * C_);

    ull xdv = xgu[(size_t)dst * 32 + lane];
    ull acc0 = fma2(pack2(ws0, ws0), xdv, 0ULL);
    ull acc1 = fma2(pack2(ws1, ws1), xdv, 0ULL);
    ull acc2 = fma2(pack2(ws2, ws2), xdv, 0ULL);
    ull acc3 = fma2(pack2(ws3, ws3), xdv, 0ULL);

    float p0 = 0.f, p1 = 0.f, p2 = 0.f, p3 = 0.f;

    for (int base = start; base < end; base += 32) {
        int e = base + lane;
        int src = 0;
        float w0 = 0.f, w1 = 0.f, w2 = 0.f, w3 = 0.f;
        if (e < end) {
            src = g_col[e];
            float4 a = s_as[src];
            w0 = __expf(lrelu(a.x + ad.x));
            w1 = __expf(lrelu(a.y + ad.y));
            w2 = __expf(lrelu(a.z + ad.z));
            w3 = __expf(lrelu(a.w + ad.w));
        }
        p0 += w0; p1 += w1; p2 += w2; p3 += w3;
        ulonglong2 pA, pB;
        pA.x = pack2(w0, w0); pA.y = pack2(w1, w1);
        pB.x = pack2(w2, w2); pB.y = pack2(w3, w3);
        *(ulonglong2*)&s_wp[warp][lane][0] = pA;
        *(ulonglong2*)&s_wp[warp][lane][2] = pB;
        s_src[warp][lane] = src;
        __syncwarp();

        int cnt = min(32, end - base);
        int sj = s_src[warp][0];
        ull xv = xgu[(size_t)sj * 32 + lane];
        for (int j = 0; j < cnt; j++) {
            int jn = min(j + 1, cnt - 1);
            int sn = s_src[warp][jn];
            ull xn = xgu[(size_t)sn * 32 + lane];
            ulonglong2 wA = *(const ulonglong2*)&s_wp[warp][j][0];
            ulonglong2 wB = *(const ulonglong2*)&s_wp[warp][j][2];
            acc0 = fma2(wA.x, xv, acc0);
            acc1 = fma2(wA.y, xv, acc1);
            acc2 = fma2(wB.x, xv, acc2);
            acc3 = fma2(wB.y, xv, acc3);
            xv = xn;
        }
        __syncwarp();
    }

    #pragma unroll
    for (int o = 16; o > 0; o >>= 1) {
        p0 += __shfl_xor_sync(0xffffffffu, p0, o);
        p1 += __shfl_xor_sync(0xffffffffu, p1, o);
        p2 += __shfl_xor_sync(0xffffffffu, p2, o);
        p3 += __shfl_xor_sync(0xffffffffu, p3, o);
    }
    float i0 = 1.0f / (p0 + ws0);
    float i1 = 1.0f / (p1 + ws1);
    float i2 = 1.0f / (p2 + ws2);
    float i3 = 1.0f / (p3 + ws3);

    float lo, hi;
    float* zp = g_z + ((size_t)g * N_ + dst) * HC_ + 2 * lane;
    unpack2(acc0, lo, hi); *(float2*)(zp +   0) = make_float2(lo * i0, hi * i0);
    unpack2(acc1, lo, hi); *(float2*)(zp +  64) = make_float2(lo * i1, hi * i1);
    unpack2(acc2, lo, hi); *(float2*)(zp + 128) = make_float2(lo * i2, hi * i2);
    unpack2(acc3, lo, hi); *(float2*)(zp + 192) = make_float2(lo * i3, hi * i3);
}

// ============================================================
// K3: out = z @ Wt + bias -> [B,Co,T,N], tensor cores.
// z fp32 in smem (A split in regs); W packed uint4 frags in smem.
// CTA 256 thr, tile 128n x 64co; warp 16n x 64co. KCH=32 (8 chunks).
// grid (4, 96) = 384 blocks; __launch_bounds__(256,3) -> 444 resident,
// single wave + 6 warps/SMSP.
// ============================================================
#define KCH 32
__global__ void __launch_bounds__(256, 3) gemm2_tc_kernel(const float* __restrict__ bias,
                                                          float* __restrict__ out) {
    __shared__ float s_z[128][36];        // [n][k] pitch 36: A LDS.32 bank = lane
    __shared__ uint4 s_w[4][4][66];       // [q][tig][co] pitch 66: LDS.128 conflict-free

    int g   = blockIdx.y;
    int qt  = blockIdx.x;          // n-quarter
    int b   = g / T_;
    int t   = g - b * T_;
    int tid = threadIdx.x;
    int w    = tid >> 5;
    int lane = tid & 31;
    int gid  = lane >> 2;   // 0..7
    int tig  = lane & 3;    // 0..3

    float acc[8][4];
    #pragma unroll
    for (int ct = 0; ct < 8; ct++)
        #pragma unroll
        for (int j = 0; j < 4; j++) acc[ct][j] = 0.0f;

    const float* zbase = g_z + ((size_t)g * N_ + qt * 128) * HC_;

    for (int kk = 0; kk < HC_ / KCH; kk++) {
        __syncthreads();
        // stage z chunk [128 n][32 k] fp32 (1024 float4)
        #pragma unroll
        for (int i = tid; i < 1024; i += 256) {
            int n = i >> 3, q4 = i & 7;
            *(float4*)&s_z[n][q4 * 4] = *(const float4*)(zbase + (size_t)n * HC_ + kk * KCH + q4 * 4);
        }
        // stage packed w frags (1024 uint4)
        #pragma unroll
        for (int i = tid; i < 1024; i += 256) {
            int co = i & 63, tg = (i >> 6) & 3, q = i >> 8;
            s_w[q][tg][co] = g_Wp[kk * 1024 + i];
        }
        __syncthreads();

        #pragma unroll
        for (int q = 0; q < 4; q++) {
            int k0 = q * 8;
            int rb = w * 16 + gid;
            unsigned ah0, ah1, ah2, ah3, al0, al1, al2, al3;
            tf32_split(s_z[rb    ][k0 + tig    ], ah0, al0);
            tf32_split(s_z[rb + 8][k0 + tig    ], ah1, al1);
            tf32_split(s_z[rb    ][k0 + tig + 4], ah2, al2);
            tf32_split(s_z[rb + 8][k0 + tig + 4], ah3, al3);
            #pragma unroll
            for (int ct = 0; ct < 8; ct++) {
                uint4 wv = s_w[q][tig][ct * 8 + gid];   // (bh0, bh1, bl0, bl1)
                mma_tf32(acc[ct][0], acc[ct][1], acc[ct][2], acc[ct][3],
                         ah0, ah1, ah2, ah3, wv.x, wv.y);
                mma_tf32(acc[ct][0], acc[ct][1], acc[ct][2], acc[ct][3],
                         al0, al1, al2, al3, wv.x, wv.y);
                mma_tf32(acc[ct][0], acc[ct][1], acc[ct][2], acc[ct][3],
                         ah0, ah1, ah2, ah3, wv.z, wv.w);
            }
        }
    }

    // epilogue: direct STG with bias
    int n_g = qt * 128 + w * 16 + gid;
    #pragma unroll
    for (int ct = 0; ct < 8; ct++) {
        int co = ct * 8 + 2 * tig;
        float bv0 = __ldg(&bias[co]);
        float bv1 = __ldg(&bias[co + 1]);
        float* o0 = out + (((size_t)b * CO_ + co)     * T_ + t) * N_ + n_g;
        float* o1 = out + (((size_t)b * CO_ + co + 1) * T_ + t) * N_ + n_g;
        o0[0] = acc[ct][0] + bv0;
        o1[0] = acc[ct][1] + bv1;
        o0[8] = acc[ct][2] + bv0;
        o1[8] = acc[ct][3] + bv1;
    }
}

// ============================================================
extern "C" void kernel_launch(void* const* d_in, const int* in_sizes, int n_in,
                              void* d_out, int out_size) {
    const float* x        = (const float*)d_in[0];
    const int*   ei       = (const int*)  d_in[1];
    const float* W        = (const float*)d_in[2];
    const float* att_src  = (const float*)d_in[3];
    const float* att_dst  = (const float*)d_in[4];
    const float* bias     = (const float*)d_in[5];
    float*       out      = (float*)d_out;
    int E = in_sizes[1] / 2;

    setup_kernel<<<2, 512>>>(ei, E, W, att_src, att_dst);
    xt_asrc_kernel<<<dim3(N_ / 128, G_), 256>>>(x);
    aggregate_kernel<<<dim3(N_ / 8, G_), 256>>>();
    gemm2_tc_kernel<<<dim3(N_ / 128, G_), 256>>>(bias, out);
}

// round 15
// speedup vs baseline: 1.7183x; 1.0175x over previous
#include <cuda_runtime.h>
#include <cstdint>

#define B_  8
#define C_  64
#define T_  12
#define N_  512
#define G_  (B_ * T_)      // 96
#define H_  4
#define CO_ 64
#define HC_ (H_ * CO_)     // 256
#define NEG_SLOPE 0.2f
#define EMAX 16384

typedef unsigned long long ull;

// ---------------- device scratch ----------------
__device__ float    g_xt[(size_t)G_ * N_ * C_];    // [G,N,64]
__device__ float    g_z [(size_t)G_ * N_ * HC_];   // [G,N,256] fp32
__device__ float    g_asrc[(size_t)G_ * N_ * H_];  // [G,N,4]
__device__ float    g_adst[(size_t)G_ * N_ * H_];
__device__ float    g_u[2 * H_ * C_];              // [src/dst][h][c]
__device__ uint4    g_Wp[8192];                    // [kk][q][tig][co] packed (wh,wh+4,wl,wl+4)
__device__ int      g_rowptr[N_ + 1];
__device__ int      g_col[EMAX];

__device__ __forceinline__ float lrelu(float x) {
    return x > 0.0f ? x : NEG_SLOPE * x;
}
__device__ __forceinline__ ull pack2(float lo, float hi) {
    ull d;
    asm("mov.b64 %0, {%1, %2};" : "=l"(d) : "r"(__float_as_uint(lo)), "r"(__float_as_uint(hi)));
    return d;
}
__device__ __forceinline__ void unpack2(ull v, float& lo, float& hi) {
    unsigned a, b;
    asm("mov.b64 {%0, %1}, %2;" : "=r"(a), "=r"(b) : "l"(v));
    lo = __uint_as_float(a); hi = __uint_as_float(b);
}
__device__ __forceinline__ ull fma2(ull a, ull b, ull c) {
    ull d;
    asm("fma.rn.f32x2 %0, %1, %2, %3;" : "=l"(d) : "l"(a), "l"(b), "l"(c));
    return d;
}
__device__ __forceinline__ void tf32_split(float v, unsigned& hi, unsigned& lo) {
    asm("cvt.rna.tf32.f32 %0, %1;" : "=r"(hi) : "f"(v));
    float r = v - __uint_as_float(hi);
    asm("cvt.rna.tf32.f32 %0, %1;" : "=r"(lo) : "f"(r));
}
__device__ __forceinline__ void mma_tf32(float& d0, float& d1, float& d2, float& d3,
                                         unsigned a0, unsigned a1, unsigned a2, unsigned a3,
                                         unsigned b0, unsigned b1) {
    asm volatile("mma.sync.aligned.m16n8k8.row.col.f32.tf32.tf32.f32 "
                 "{%0,%1,%2,%3}, {%4,%5,%6,%7}, {%8,%9}, {%0,%1,%2,%3};"
                 : "+f"(d0), "+f"(d1), "+f"(d2), "+f"(d3)
                 : "r"(a0), "r"(a1), "r"(a2), "r"(a3), "r"(b0), "r"(b1));
}
__device__ __forceinline__ void cp_async16(uint32_t smem_addr, const void* gptr) {
    asm volatile("cp.async.cg.shared.global [%0], [%1], 16;"
                 :: "r"(smem_addr), "l"(gptr) : "memory");
}

// ============================================================
// K0: setup. block 0: CSR build. block 1: prep u + packed W. 512 thr.
// ============================================================
__global__ void setup_kernel(const int* __restrict__ ei, int E,
                             const float* __restrict__ W,
                             const float* __restrict__ att_src,
                             const float* __restrict__ att_dst) {
    int tid = threadIdx.x;
    if (blockIdx.x == 0) {
        __shared__ int cnt[N_];
        __shared__ int cur[N_];
        __shared__ int wsum[16];
        cnt[tid] = 0;
        __syncthreads();
        const int* dst = ei + E;
        for (int e = tid; e < E; e += N_) atomicAdd(&cnt[dst[e]], 1);
        __syncthreads();

        int v = cnt[tid];
        int lane = tid & 31, wid = tid >> 5;
        int inc = v;
        #pragma unroll
        for (int o = 1; o < 32; o <<= 1) {
            int u = __shfl_up_sync(0xffffffffu, inc, o);
            if (lane >= o) inc += u;
        }
        if (lane == 31) wsum[wid] = inc;
        __syncthreads();
        if (wid == 0 && lane < 16) {
            int ws = wsum[lane];
            int wi = ws;
            #pragma unroll
            for (int o = 1; o < 16; o <<= 1) {
                int u = __shfl_up_sync(0x0000ffffu, wi, o);
                if (lane >= o) wi += u;
            }
            wsum[lane] = wi - ws;
        }
        __syncthreads();
        int excl = inc - v + wsum[wid];
        g_rowptr[tid] = excl;
        cur[tid] = excl;
        if (tid == N_ - 1) g_rowptr[N_] = excl + v;
        __syncthreads();

        for (int e = tid; e < E; e += N_) {
            int d = dst[e];
            int p = atomicAdd(&cur[d], 1);
            g_col[p] = ei[e];
        }
    } else {
        __shared__ float satt[2 * H_ * CO_];
        satt[tid] = (tid < 256) ? att_src[tid] : att_dst[tid - 256];
        __syncthreads();

        {
            int k = tid;                 // 512 = 2*4*64
            int p = k >> 8;
            int h = (k >> 6) & 3;
            int c = k & 63;
            const float* wrow = W + (size_t)c * HC_ + h * CO_;
            const float* av = satt + p * 256 + h * CO_;
            float s = 0.0f;
            #pragma unroll 16
            for (int co = 0; co < CO_; co++) s += wrow[co] * av[co];
            g_u[k] = s;
        }
        // packed W: g_Wp[((kk*4+q)*4+tig)*64+co] = (wh[k],wh[k+4],wl[k],wl[k+4]),
        // k = kk*32 + q*8 + tig, wt = 0.25*W[c][h*64+co] with k = h*64+c
        for (int idx = tid; idx < 8192; idx += 512) {
            int co  = idx & 63;
            int tig = (idx >> 6) & 3;
            int q   = (idx >> 8) & 3;
            int kk  = idx >> 10;
            int k   = kk * 32 + q * 8 + tig;
            int h  = k >> 6,  c  = k & 63;
            int k2 = k + 4;
            int h2 = k2 >> 6, c2 = k2 & 63;
            float w0 = 0.25f * W[(size_t)c  * HC_ + h  * CO_ + co];
            float w1 = 0.25f * W[(size_t)c2 * HC_ + h2 * CO_ + co];
            uint4 pv;
            tf32_split(w0, pv.x, pv.z);
            tf32_split(w1, pv.y, pv.w);
            g_Wp[idx] = pv;
        }
    }
}

// ============================================================
// K1: per g: transpose x -> xt, asrc/adst = x . u
// grid (4, 96), block 256.
// ============================================================
__global__ void xt_asrc_kernel(const float* __restrict__ x) {
    __shared__ float xs[64][129];
    __shared__ float su[8][64];
    int g  = blockIdx.y;
    int n0 = blockIdx.x * 128;
    int b  = g / T_;
    int t  = g - b * T_;
    int tid = threadIdx.x;

    for (int i = tid; i < 512; i += 256) su[i >> 6][i & 63] = g_u[i];
    #pragma unroll
    for (int i = tid; i < 64 * 32; i += 256) {
        int c = i >> 5, q = i & 31;
        float4 v = *(const float4*)(x + (((size_t)b * C_ + c) * T_ + t) * N_ + n0 + q * 4);
        xs[c][q * 4 + 0] = v.x; xs[c][q * 4 + 1] = v.y;
        xs[c][q * 4 + 2] = v.z; xs[c][q * 4 + 3] = v.w;
    }
    __syncthreads();

    {
        int n = tid & 127;
        int p = tid >> 7;
        float a0 = 0.f, a1 = 0.f, a2 = 0.f, a3 = 0.f;
        #pragma unroll 16
        for (int c = 0; c < 64; c++) {
            float xv = xs[c][n];
            a0 = fmaf(xv, su[p * 4 + 0][c], a0);
            a1 = fmaf(xv, su[p * 4 + 1][c], a1);
            a2 = fmaf(xv, su[p * 4 + 2][c], a2);
            a3 = fmaf(xv, su[p * 4 + 3][c], a3);
        }
        float* dstp = (p == 0 ? g_asrc : g_adst) + ((size_t)g * N_ + n0 + n) * H_;
        dstp[0] = a0; dstp[1] = a1; dstp[2] = a2; dstp[3] = a3;
    }

    #pragma unroll
    for (int i = tid; i < 128 * 16; i += 256) {
        int n = i >> 4, q = i & 15;
        float4 v = {xs[q * 4 + 0][n], xs[q * 4 + 1][n], xs[q * 4 + 2][n], xs[q * 4 + 3][n]};
        *(float4*)(g_xt + ((size_t)g * N_ + n0 + n) * C_ + q * 4) = v;
    }
}

// ============================================================
// K2: aggregate in x-space, warp per (g,dst). (unchanged, proven)
// ============================================================
__global__ void __launch_bounds__(256) aggregate_kernel() {
    __shared__ float4 s_as[N_];
    __shared__ ull    s_wp[8][32][4];
    __shared__ int    s_src[8][32];
    int g    = blockIdx.y;
    int tid  = threadIdx.x;
    int warp = tid >> 5, lane = tid & 31;

    const float4* asrc_g = (const float4*)(g_asrc + (size_t)g * N_ * H_);
    for (int i = tid; i < N_; i += 256) s_as[i] = asrc_g[i];
    __syncthreads();

    int dst   = (blockIdx.x << 3) + warp;
    int start = g_rowptr[dst];
    int end   = g_rowptr[dst + 1];

    float4 ad = *(const float4*)(g_adst + ((size_t)g * N_ + dst) * H_);
    float4 sa = s_as[dst];
    float ws0 = __expf(lrelu(sa.x + ad.x));
    float ws1 = __expf(lrelu(sa.y + ad.y));
    float ws2 = __expf(lrelu(sa.z + ad.z));
    float ws3 = __expf(lrelu(sa.w + ad.w));

    const ull* xgu = (const ull*)(g_xt + (size_t)g * N_ * C_);

    ull xdv = xgu[(size_t)dst * 32 + lane];
    ull acc0 = fma2(pack2(ws0, ws0), xdv, 0ULL);
    ull acc1 = fma2(pack2(ws1, ws1), xdv, 0ULL);
    ull acc2 = fma2(pack2(ws2, ws2), xdv, 0ULL);
    ull acc3 = fma2(pack2(ws3, ws3), xdv, 0ULL);

    float p0 = 0.f, p1 = 0.f, p2 = 0.f, p3 = 0.f;

    for (int base = start; base < end; base += 32) {
        int e = base + lane;
        int src = 0;
        float w0 = 0.f, w1 = 0.f, w2 = 0.f, w3 = 0.f;
        if (e < end) {
            src = g_col[e];
            float4 a = s_as[src];
            w0 = __expf(lrelu(a.x + ad.x));
            w1 = __expf(lrelu(a.y + ad.y));
            w2 = __expf(lrelu(a.z + ad.z));
            w3 = __expf(lrelu(a.w + ad.w));
        }
        p0 += w0; p1 += w1; p2 += w2; p3 += w3;
        ulonglong2 pA, pB;
        pA.x = pack2(w0, w0); pA.y = pack2(w1, w1);
        pB.x = pack2(w2, w2); pB.y = pack2(w3, w3);
        *(ulonglong2*)&s_wp[warp][lane][0] = pA;
        *(ulonglong2*)&s_wp[warp][lane][2] = pB;
        s_src[warp][lane] = src;
        __syncwarp();

        int cnt = min(32, end - base);
        int sj = s_src[warp][0];
        ull xv = xgu[(size_t)sj * 32 + lane];
        for (int j = 0; j < cnt; j++) {
            int jn = min(j + 1, cnt - 1);
            int sn = s_src[warp][jn];
            ull xn = xgu[(size_t)sn * 32 + lane];
            ulonglong2 wA = *(const ulonglong2*)&s_wp[warp][j][0];
            ulonglong2 wB = *(const ulonglong2*)&s_wp[warp][j][2];
            acc0 = fma2(wA.x, xv, acc0);
            acc1 = fma2(wA.y, xv, acc1);
            acc2 = fma2(wB.x, xv, acc2);
            acc3 = fma2(wB.y, xv, acc3);
            xv = xn;
        }
        __syncwarp();
    }

    #pragma unroll
    for (int o = 16; o > 0; o >>= 1) {
        p0 += __shfl_xor_sync(0xffffffffu, p0, o);
        p1 += __shfl_xor_sync(0xffffffffu, p1, o);
        p2 += __shfl_xor_sync(0xffffffffu, p2, o);
        p3 += __shfl_xor_sync(0xffffffffu, p3, o);
    }
    float i0 = 1.0f / (p0 + ws0);
    float i1 = 1.0f / (p1 + ws1);
    float i2 = 1.0f / (p2 + ws2);
    float i3 = 1.0f / (p3 + ws3);

    float lo, hi;
    float* zp = g_z + ((size_t)g * N_ + dst) * HC_ + 2 * lane;
    unpack2(acc0, lo, hi); *(float2*)(zp +   0) = make_float2(lo * i0, hi * i0);
    unpack2(acc1, lo, hi); *(float2*)(zp +  64) = make_float2(lo * i1, hi * i1);
    unpack2(acc2, lo, hi); *(float2*)(zp + 128) = make_float2(lo * i2, hi * i2);
    unpack2(acc3, lo, hi); *(float2*)(zp + 192) = make_float2(lo * i3, hi * i3);
}

// ============================================================
// K3: out = z @ Wt + bias -> [B,Co,T,N], tensor cores.
// 2-stage cp.async pipeline (z + packed-W), dynamic smem 2x35328 B.
// CTA 256 thr, tile 128n x 64co; warp 16n x 64co. KCH=32 (8 chunks).
// grid (4, 96) = 384 blocks; 3 CTAs/SM -> single wave.
// ============================================================
#define KCH 32
#define Z_ELEMS (128 * 36)                 // floats per stage
#define Z_BYTES (Z_ELEMS * 4)              // 18432
#define W_ELEMS (4 * 4 * 66)               // uint4 per stage
#define W_BYTES (W_ELEMS * 16)             // 16896
#define STAGE_BYTES (Z_BYTES + W_BYTES)    // 35328

__global__ void __launch_bounds__(256, 3) gemm2_tc_kernel(const float* __restrict__ bias,
                                                          float* __restrict__ out) {
    extern __shared__ __align__(16) char dsm[];

    int g   = blockIdx.y;
    int qt  = blockIdx.x;          // n-quarter
    int b   = g / T_;
    int t   = g - b * T_;
    int tid = threadIdx.x;
    int w    = tid >> 5;
    int lane = tid & 31;
    int gid  = lane >> 2;   // 0..7
    int tig  = lane & 3;    // 0..3

    float acc[8][4];
    #pragma unroll
    for (int ct = 0; ct < 8; ct++)
        #pragma unroll
        for (int j = 0; j < 4; j++) acc[ct][j] = 0.0f;

    const float* zbase = g_z + ((size_t)g * N_ + qt * 128) * HC_;

    // staging indices (fixed per thread)
    // z: 4 cp.async of 16B each; i = tid + 256*j -> n = i>>3, q4 = i&7
    // w: 4 cp.async of 16B each; idx = tid + 256*j -> co=idx&63, tg=(idx>>6)&3, q=idx>>8
    auto issue_chunk = [&](int kk, int s) {
        char* sb = dsm + s * STAGE_BYTES;
        float* s_z = (float*)sb;
        uint4* s_w = (uint4*)(sb + Z_BYTES);
        #pragma unroll
        for (int j = 0; j < 4; j++) {
            int i = tid + 256 * j;
            int n = i >> 3, q4 = i & 7;
            uint32_t dst = (uint32_t)__cvta_generic_to_shared(&s_z[n * 36 + q4 * 4]);
            cp_async16(dst, zbase + (size_t)n * HC_ + kk * KCH + q4 * 4);
        }
        #pragma unroll
        for (int j = 0; j < 4; j++) {
            int idx = tid + 256 * j;
            int co = idx & 63, tg = (idx >> 6) & 3, q = idx >> 8;
            uint32_t dst = (uint32_t)__cvta_generic_to_shared(&s_w[(q * 4 + tg) * 66 + co]);
            cp_async16(dst, g_Wp + kk * 1024 + idx);
        }
        asm volatile("cp.async.commit_group;" ::: "memory");
    };

    issue_chunk(0, 0);

    for (int kk = 0; kk < HC_ / KCH; kk++) {
        // wait for chunk kk's copies (only pending group), make visible
        asm volatile("cp.async.wait_group 0;" ::: "memory");
        __syncthreads();
        // overlap: issue chunk kk+1 into the other buffer (its previous
        // contents, chunk kk-1, are done: all warps passed the barrier
        // above only after finishing compute of kk-1)
        if (kk + 1 < HC_ / KCH) issue_chunk(kk + 1, (kk + 1) & 1);

        char* sb = dsm + (kk & 1) * STAGE_BYTES;
        float* s_z = (float*)sb;
        uint4* s_w = (uint4*)(sb + Z_BYTES);

        #pragma unroll
        for (int q = 0; q < 4; q++) {
            int k0 = q * 8;
            int rb = w * 16 + gid;
            unsigned ah0, ah1, ah2, ah3, al0, al1, al2, al3;
            tf32_split(s_z[(rb    ) * 36 + k0 + tig    ], ah0, al0);
            tf32_split(s_z[(rb + 8) * 36 + k0 + tig    ], ah1, al1);
            tf32_split(s_z[(rb    ) * 36 + k0 + tig + 4], ah2, al2);
            tf32_split(s_z[(rb + 8) * 36 + k0 + tig + 4], ah3, al3);
            #pragma unroll
            for (int ct = 0; ct < 8; ct++) {
                uint4 wv = s_w[(q * 4 + tig) * 66 + ct * 8 + gid];   // (bh0,bh1,bl0,bl1)
                mma_tf32(acc[ct][0], acc[ct][1], acc[ct][2], acc[ct][3],
                         ah0, ah1, ah2, ah3, wv.x, wv.y);
                mma_tf32(acc[ct][0], acc[ct][1], acc[ct][2], acc[ct][3],
                         al0, al1, al2, al3, wv.x, wv.y);
                mma_tf32(acc[ct][0], acc[ct][1], acc[ct][2], acc[ct][3],
                         ah0, ah1, ah2, ah3, wv.z, wv.w);
            }
        }
    }

    // epilogue: direct STG with bias
    int n_g = qt * 128 + w * 16 + gid;
    #pragma unroll
    for (int ct = 0; ct < 8; ct++) {
        int co = ct * 8 + 2 * tig;
        float bv0 = __ldg(&bias[co]);
        float bv1 = __ldg(&bias[co + 1]);
        float* o0 = out + (((size_t)b * CO_ + co)     * T_ + t) * N_ + n_g;
        float* o1 = out + (((size_t)b * CO_ + co + 1) * T_ + t) * N_ + n_g;
        o0[0] = acc[ct][0] + bv0;
        o1[0] = acc[ct][1] + bv1;
        o0[8] = acc[ct][2] + bv0;
        o1[8] = acc[ct][3] + bv1;
    }
}

// ============================================================
extern "C" void kernel_launch(void* const* d_in, const int* in_sizes, int n_in,
                              void* d_out, int out_size) {
    const float* x        = (const float*)d_in[0];
    const int*   ei       = (const int*)  d_in[1];
    const float* W        = (const float*)d_in[2];
    const float* att_src  = (const float*)d_in[3];
    const float* att_dst  = (const float*)d_in[4];
    const float* bias     = (const float*)d_in[5];
    float*       out      = (float*)d_out;
    int E = in_sizes[1] / 2;

    cudaFuncSetAttribute(gemm2_tc_kernel,
                         cudaFuncAttributeMaxDynamicSharedMemorySize,
                         2 * STAGE_BYTES);

    setup_kernel<<<2, 512>>>(ei, E, W, att_src, att_dst);
    xt_asrc_kernel<<<dim3(N_ / 128, G_), 256>>>(x);
    aggregate_kernel<<<dim3(N_ / 8, G_), 256>>>();
    gemm2_tc_kernel<<<dim3(N_ / 128, G_), 256, 2 * STAGE_BYTES>>>(bias, out);
}